// round 10
// baseline (speedup 1.0000x reference)
#include <cuda_runtime.h>
#include <cuda_bf16.h>
#include <cstdint>

// ---------------- problem constants ----------------
#define NV      50000      // nodes
#define NE      200000     // edges
#define NB      1024       // graphs
#define DD      24         // node feature dim
#define EF      8          // edge feature dim
#define EH      128        // edge MLP hidden
#define DW      576        // D*D
#define MT      1563       // m-tiles of 128 edges
#define ME_PAD  (MT*128)   // 200064 padded edge rows
#define NT      9          // n-tiles of 64 over DW=576

// ---------------- device scratch (zero-init at module load) ----------------
__device__ float g_H[(size_t)ME_PAD * EH];      // 102 MB  relu(ea@W1+b1), pad rows stay 0
__device__ float g_We[(size_t)ME_PAD * DW];     // 461 MB  per-edge 24x24 weights
__device__ float g_agg[NV * DD];
__device__ float g_cnt[NV];
__device__ float g_x1[NV * DD];
__device__ float g_x2[NV * DD];
__device__ int   g_start[NB + 1];
__device__ float g_qstar[NB * 2 * DD];
__device__ float g_h[NB * DD];
__device__ float g_c[NB * DD];

// ---------------- zero kernels ----------------
__global__ void zero_all_kernel() {
    int i = blockIdx.x * blockDim.x + threadIdx.x;
    int stride = gridDim.x * blockDim.x;
    for (int k = i; k < NV * DD; k += stride) g_agg[k] = 0.f;
    for (int k = i; k < NV; k += stride) g_cnt[k] = 0.f;
    for (int k = i; k < NB * 2 * DD; k += stride) g_qstar[k] = 0.f;
    for (int k = i; k < NB * DD; k += stride) { g_h[k] = 0.f; g_c[k] = 0.f; }
}
__global__ void zero_agg_kernel() {
    int i = blockIdx.x * blockDim.x + threadIdx.x;
    int stride = gridDim.x * blockDim.x;
    for (int k = i; k < NV * DD; k += stride) g_agg[k] = 0.f;
}

// ---------------- stage A1: H = relu(edge_attr @ W1 + b1) ----------------
__global__ void __launch_bounds__(128) edge_mlp1_kernel(
    const float* __restrict__ ea, const float* __restrict__ w1,
    const float* __restrict__ b1)
{
    __shared__ float sw[EF * EH];
    __shared__ float sb[EH];
    __shared__ float sea[8 * EF];
    int t = threadIdx.x;
    for (int i = t; i < EF * EH; i += 128) sw[i] = w1[i];
    sb[t] = b1[t];
    int e0 = blockIdx.x * 8;
    for (int i = t; i < 8 * EF; i += 128) {
        int ee = e0 + i / EF;
        if (ee < NE) sea[i] = ea[(size_t)ee * EF + (i % EF)];
    }
    __syncthreads();
    #pragma unroll
    for (int q = 0; q < 8; q++) {
        int e = e0 + q;
        if (e >= NE) break;
        float acc = sb[t];
        #pragma unroll
        for (int i = 0; i < EF; i++) acc += sea[q * EF + i] * sw[i * EH + t];
        g_H[(size_t)e * EH + t] = fmaxf(acc, 0.f);
    }
}

// ---------------- stage A2: We = H @ W2 + b2  (fp32x2, dup-A, dbl-buffer) --
// M=ME_PAD, K=128, N=576.  Block tile 128x64, 128 threads, 8x8 microtile.
__global__ void __launch_bounds__(128) gemm_we_kernel(
    const float* __restrict__ W2, const float* __restrict__ be2)
{
    // A stored as duplicated pairs (a,a) so the inner loop needs no mov.b64.
    __shared__ float2 As[2][16][128];   // 2 x 16KB
    __shared__ float  Bs[2][16][68];    // 2 x 4.3KB (row stride 272B, 16B-aligned)

    int t  = threadIdx.x;
    int bm = blockIdx.y, bn = blockIdx.x;
    int tx = t & 7;        // n-tile: 8 threads * 8 cols
    int ty = t >> 3;       // m-tile: 16 threads * 8 rows

    unsigned long long acc[8][4];
    #pragma unroll
    for (int i = 0; i < 8; i++)
        #pragma unroll
        for (int j = 0; j < 4; j++) acc[i][j] = 0ULL;

    const float* Ag = g_H + (size_t)bm * 128 * EH;
    const float* Bg = W2 + bn * 64;

    // per-thread load indices (stage-invariant)
    const int arow0 = t >> 2;          // +32*p
    const int akq   = (t & 3) * 4;
    const int bkr0  = t >> 4;          // +8*p
    const int bc4   = (t & 15) * 4;

    float4 ar[4];
    float4 br[2];

    // ---- prologue: load stage 0 ----
    #pragma unroll
    for (int p = 0; p < 4; p++)
        ar[p] = *reinterpret_cast<const float4*>(Ag + (size_t)(arow0 + 32 * p) * EH + akq);
    #pragma unroll
    for (int p = 0; p < 2; p++)
        br[p] = *reinterpret_cast<const float4*>(Bg + (size_t)(bkr0 + 8 * p) * DW + bc4);
    #pragma unroll
    for (int p = 0; p < 4; p++) {
        int row = arow0 + 32 * p;
        As[0][akq + 0][row] = make_float2(ar[p].x, ar[p].x);
        As[0][akq + 1][row] = make_float2(ar[p].y, ar[p].y);
        As[0][akq + 2][row] = make_float2(ar[p].z, ar[p].z);
        As[0][akq + 3][row] = make_float2(ar[p].w, ar[p].w);
    }
    #pragma unroll
    for (int p = 0; p < 2; p++)
        *reinterpret_cast<float4*>(&Bs[0][bkr0 + 8 * p][bc4]) = br[p];
    __syncthreads();

    #pragma unroll
    for (int s = 0; s < 8; s++) {
        int buf = s & 1;
        // prefetch next stage into registers (latency overlapped with compute)
        if (s < 7) {
            int kk = (s + 1) * 16;
            #pragma unroll
            for (int p = 0; p < 4; p++)
                ar[p] = *reinterpret_cast<const float4*>(Ag + (size_t)(arow0 + 32 * p) * EH + kk + akq);
            #pragma unroll
            for (int p = 0; p < 2; p++)
                br[p] = *reinterpret_cast<const float4*>(Bg + (size_t)(kk + bkr0 + 8 * p) * DW + bc4);
        }
        // compute on current buffer
        #pragma unroll
        for (int k = 0; k < 16; k++) {
            unsigned long long a2[8], b2[4];
            #pragma unroll
            for (int i = 0; i < 8; i++)
                a2[i] = *reinterpret_cast<const unsigned long long*>(&As[buf][k][ty * 8 + i]);
            #pragma unroll
            for (int j = 0; j < 4; j++)
                b2[j] = *reinterpret_cast<const unsigned long long*>(&Bs[buf][k][tx * 8 + 2 * j]);
            #pragma unroll
            for (int i = 0; i < 8; i++)
                #pragma unroll
                for (int j = 0; j < 4; j++)
                    asm("fma.rn.f32x2 %0, %1, %2, %0;"
                        : "+l"(acc[i][j]) : "l"(a2[i]), "l"(b2[j]));
        }
        // store staged registers into the other buffer
        if (s < 7) {
            int nb = buf ^ 1;
            #pragma unroll
            for (int p = 0; p < 4; p++) {
                int row = arow0 + 32 * p;
                As[nb][akq + 0][row] = make_float2(ar[p].x, ar[p].x);
                As[nb][akq + 1][row] = make_float2(ar[p].y, ar[p].y);
                As[nb][akq + 2][row] = make_float2(ar[p].z, ar[p].z);
                As[nb][akq + 3][row] = make_float2(ar[p].w, ar[p].w);
            }
            #pragma unroll
            for (int p = 0; p < 2; p++)
                *reinterpret_cast<float4*>(&Bs[nb][bkr0 + 8 * p][bc4]) = br[p];
            __syncthreads();
        }
    }

    int ncol = bn * 64 + tx * 8;
    float bias[8];
    #pragma unroll
    for (int j = 0; j < 8; j++) bias[j] = be2[ncol + j];

    #pragma unroll
    for (int i = 0; i < 8; i++) {
        size_t row = (size_t)(bm * 128 + ty * 8 + i);
        float out[8];
        #pragma unroll
        for (int j = 0; j < 4; j++) {
            out[2 * j]     = __uint_as_float((unsigned int)(acc[i][j] & 0xffffffffULL)) + bias[2 * j];
            out[2 * j + 1] = __uint_as_float((unsigned int)(acc[i][j] >> 32)) + bias[2 * j + 1];
        }
        float4* dst = reinterpret_cast<float4*>(&g_We[row * DW + ncol]);
        dst[0] = make_float4(out[0], out[1], out[2], out[3]);
        dst[1] = make_float4(out[4], out[5], out[6], out[7]);
    }
}

// ---------------- graph boundaries from sorted batch (int32) -------------
__global__ void graph_bounds_kernel(const int* __restrict__ batch) {
    int i = blockIdx.x * blockDim.x + threadIdx.x;
    if (i >= NV) return;
    int bi = batch[i];
    if (i == 0) {
        for (int g = 0; g <= bi; g++) g_start[g] = 0;
    } else {
        int bp = batch[i - 1];
        for (int g = bp + 1; g <= bi; g++) g_start[g] = i;
    }
    if (i == NV - 1) {
        for (int g = bi + 1; g <= NB; g++) g_start[g] = NV;
    }
}

// ---------------- message pass: agg[dst] += x[src] @ We[e] ----------------
__global__ void msg_pass_kernel(const float* __restrict__ x,
                                const int* __restrict__ ei, int addCnt)
{
    int w = (blockIdx.x * blockDim.x + threadIdx.x) >> 5;
    int lane = threadIdx.x & 31;
    if (w >= NE) return;
    int src = ei[w];
    int dst = ei[NE + w];
    float xv = (lane < DD) ? x[(size_t)src * DD + lane] : 0.f;
    float acc = 0.f;
    const float* We = g_We + (size_t)w * DW;
    #pragma unroll
    for (int i = 0; i < DD; i++) {
        float xi = __shfl_sync(0xffffffffu, xv, i);
        float wv = (lane < DD) ? We[i * DD + lane] : 0.f;
        acc += xi * wv;
    }
    if (lane < DD) atomicAdd(&g_agg[dst * DD + lane], acc);
    if (addCnt && lane == 0) atomicAdd(&g_cnt[dst], 1.f);
}

// ---------------- node update: agg/cnt + x@root + bias (opt relu) ---------
__global__ void node_update_kernel(const float* __restrict__ xin,
                                   const float* __restrict__ root,
                                   const float* __restrict__ bias,
                                   float* __restrict__ xout, int doRelu)
{
    int idx = blockIdx.x * blockDim.x + threadIdx.x;
    if (idx >= NV * DD) return;
    int v = idx / DD, j = idx % DD;
    float cnt = fmaxf(g_cnt[v], 1.f);
    float acc = g_agg[idx] / cnt + bias[j];
    const float* xr = xin + (size_t)v * DD;
    #pragma unroll
    for (int i = 0; i < DD; i++) acc += xr[i] * root[i * DD + j];
    if (doRelu) acc = fmaxf(acc, 0.f);
    xout[idx] = acc;
}

// ---------------- Set2Set: one full step (LSTM + attention) ---------------
__device__ __forceinline__ float sigm(float v) { return 1.f / (1.f + expf(-v)); }

__global__ void __launch_bounds__(128) s2s_step_kernel(
    const float* __restrict__ x2,
    const float* __restrict__ wih, const float* __restrict__ whh,
    const float* __restrict__ bih, const float* __restrict__ bhh)
{
    __shared__ float sq[2 * DD], shh[DD], scc[DD], sg[4 * DD], hn[DD];
    __shared__ float red[128];
    __shared__ float wr[4][DD];
    __shared__ float ws[4];

    int b = blockIdx.x, t = threadIdx.x;
    if (t < 2 * DD) sq[t] = g_qstar[b * 2 * DD + t];
    if (t < DD) { shh[t] = g_h[b * DD + t]; scc[t] = g_c[b * DD + t]; }
    __syncthreads();

    if (t < 4 * DD) {
        float g = bih[t] + bhh[t];
        #pragma unroll 8
        for (int u = 0; u < 2 * DD; u++) g += sq[u] * wih[t * 2 * DD + u];
        #pragma unroll 8
        for (int u = 0; u < DD; u++) g += shh[u] * whh[t * DD + u];
        sg[t] = g;
    }
    __syncthreads();

    if (t < DD) {
        float ig = sigm(sg[t]);
        float fg = sigm(sg[DD + t]);
        float gg = tanhf(sg[2 * DD + t]);
        float og = sigm(sg[3 * DD + t]);
        float cn = fg * scc[t] + ig * gg;
        float hv = og * tanhf(cn);
        g_c[b * DD + t] = cn;
        g_h[b * DD + t] = hv;
        hn[t] = hv;
    }
    __syncthreads();

    int s0 = g_start[b], s1 = g_start[b + 1];

    float lmax = -3.4e38f;
    for (int n = s0 + t; n < s1; n += 128) {
        const float* xr = x2 + (size_t)n * DD;
        float e = 0.f;
        #pragma unroll
        for (int d = 0; d < DD; d++) e += xr[d] * hn[d];
        lmax = fmaxf(lmax, e);
    }
    red[t] = lmax;
    __syncthreads();
    for (int s = 64; s > 0; s >>= 1) {
        if (t < s) red[t] = fmaxf(red[t], red[t + s]);
        __syncthreads();
    }
    float emax = red[0];
    if (!(emax > -3.0e38f)) emax = 0.f;

    float lsum = 0.f;
    float lr[DD];
    #pragma unroll
    for (int d = 0; d < DD; d++) lr[d] = 0.f;
    for (int n = s0 + t; n < s1; n += 128) {
        const float* xr = x2 + (size_t)n * DD;
        float e = 0.f;
        #pragma unroll
        for (int d = 0; d < DD; d++) e += xr[d] * hn[d];
        float ex = expf(e - emax);
        lsum += ex;
        #pragma unroll
        for (int d = 0; d < DD; d++) lr[d] += ex * xr[d];
    }
    #pragma unroll
    for (int o = 16; o > 0; o >>= 1) {
        lsum += __shfl_xor_sync(0xffffffffu, lsum, o);
        #pragma unroll
        for (int d = 0; d < DD; d++) lr[d] += __shfl_xor_sync(0xffffffffu, lr[d], o);
    }
    int wid = t >> 5, lane = t & 31;
    if (lane == 0) ws[wid] = lsum;
    if (lane < DD) wr[wid][lane] = lr[lane];
    __syncthreads();

    if (t < DD) {
        float denom = ws[0] + ws[1] + ws[2] + ws[3];
        float rsum = wr[0][t] + wr[1][t] + wr[2][t] + wr[3][t];
        float r = rsum / fmaxf(denom, 1e-16f);
        g_qstar[b * 2 * DD + t] = hn[t];
        g_qstar[b * 2 * DD + DD + t] = r;
    }
}

// ---------------- heads ----------------
__global__ void heads_kernel(const float* __restrict__ wfc2, const float* __restrict__ bfc2,
                             const float* __restrict__ wfc3, const float* __restrict__ bfc3,
                             float* __restrict__ out)
{
    int b = blockIdx.x * blockDim.x + threadIdx.x;
    if (b >= NB) return;
    const float* q = g_qstar + b * 2 * DD;
    float hid[8];
    #pragma unroll
    for (int j = 0; j < 8; j++) {
        float h = bfc2[j];
        #pragma unroll 8
        for (int u = 0; u < 2 * DD; u++) h += q[u] * wfc2[u * 8 + j];
        hid[j] = fmaxf(h, 0.f);
    }
    #pragma unroll
    for (int k = 0; k < 2; k++) {
        float o = bfc3[k];
        #pragma unroll
        for (int j = 0; j < 8; j++) o += hid[j] * wfc3[j * 2 + k];
        out[b * 2 + k] = o;
    }
}

// ---------------- launch ----------------
extern "C" void kernel_launch(void* const* d_in, const int* in_sizes, int n_in,
                              void* d_out, int out_size)
{
    const float* x        = (const float*)d_in[0];
    const float* ea       = (const float*)d_in[1];
    const float* w_e1     = (const float*)d_in[2];
    const float* b_e1     = (const float*)d_in[3];
    const float* w_e2     = (const float*)d_in[4];
    const float* b_e2     = (const float*)d_in[5];
    const float* root     = (const float*)d_in[6];
    const float* bias_c   = (const float*)d_in[7];
    const float* w_ih     = (const float*)d_in[8];
    const float* w_hh     = (const float*)d_in[9];
    const float* b_ih     = (const float*)d_in[10];
    const float* b_hh     = (const float*)d_in[11];
    const float* w_fc2    = (const float*)d_in[12];
    const float* b_fc2    = (const float*)d_in[13];
    const float* w_fc3    = (const float*)d_in[14];
    const float* b_fc3    = (const float*)d_in[15];
    const int*   ei       = (const int*)d_in[16];
    const int*   bat      = (const int*)d_in[17];
    float* out            = (float*)d_out;

    float *px1 = nullptr, *px2 = nullptr;
    cudaGetSymbolAddress((void**)&px1, g_x1);
    cudaGetSymbolAddress((void**)&px2, g_x2);

    // order chosen so the big GEMM sits in the ncu-captured launch slot
    zero_all_kernel<<<1024, 256>>>();
    edge_mlp1_kernel<<<NE / 8, 128>>>(ea, w_e1, b_e1);
    graph_bounds_kernel<<<(NV + 255) / 256, 256>>>(bat);
    {
        dim3 grid(NT, MT);   // 9 x 1563
        gemm_we_kernel<<<grid, 128>>>(w_e2, b_e2);
    }

    // NNConv layer 1 (input x, relu -> g_x1)
    msg_pass_kernel<<<NE / 8, 256>>>(x, ei, 1);
    node_update_kernel<<<(NV * DD + 255) / 256, 256>>>(x, root, bias_c, px1, 1);

    // NNConv layer 2 (input g_x1 -> g_x2)
    zero_agg_kernel<<<512, 256>>>();
    msg_pass_kernel<<<NE / 8, 256>>>(px1, ei, 0);
    node_update_kernel<<<(NV * DD + 255) / 256, 256>>>(px1, root, bias_c, px2, 0);

    // Set2Set: 3 steps
    for (int s = 0; s < 3; s++)
        s2s_step_kernel<<<NB, 128>>>(px2, w_ih, w_hh, b_ih, b_hh);

    heads_kernel<<<(NB + 255) / 256, 256>>>(w_fc2, b_fc2, w_fc3, b_fc3, out);
}

// round 11
// speedup vs baseline: 1.3849x; 1.3849x over previous
#include <cuda_runtime.h>
#include <cuda_bf16.h>
#include <cstdint>

// ---------------- problem constants ----------------
#define NV      50000      // nodes
#define NE      200000     // edges
#define NB      1024       // graphs
#define DD      24         // node feature dim
#define EF      8          // edge feature dim
#define EH      128        // edge MLP hidden
#define DW      576        // D*D
#define MT      1563       // m-tiles of 128 edges
#define ME_PAD  (MT*128)   // 200064 padded edge rows
#define NT      9          // n-tiles of 64 over DW=576

// ---------------- device scratch (zero-init at module load) ----------------
__device__ float g_H[(size_t)ME_PAD * EH];      // 102 MB  relu(ea@W1+b1), pad rows stay 0
__device__ float g_We[(size_t)ME_PAD * DW];     // 461 MB  per-edge 24x24 weights
__device__ float g_agg[NV * DD];
__device__ float g_cnt[NV];
__device__ float g_x1[NV * DD];
__device__ float g_x2[NV * DD];
__device__ int   g_start[NB + 1];
__device__ float g_qstar[NB * 2 * DD];
__device__ float g_h[NB * DD];
__device__ float g_c[NB * DD];

// ---------------- zero kernels ----------------
__global__ void zero_all_kernel() {
    int i = blockIdx.x * blockDim.x + threadIdx.x;
    int stride = gridDim.x * blockDim.x;
    for (int k = i; k < NV * DD; k += stride) g_agg[k] = 0.f;
    for (int k = i; k < NV; k += stride) g_cnt[k] = 0.f;
    for (int k = i; k < NB * 2 * DD; k += stride) g_qstar[k] = 0.f;
    for (int k = i; k < NB * DD; k += stride) { g_h[k] = 0.f; g_c[k] = 0.f; }
}
__global__ void zero_agg_kernel() {
    int i = blockIdx.x * blockDim.x + threadIdx.x;
    int stride = gridDim.x * blockDim.x;
    for (int k = i; k < NV * DD; k += stride) g_agg[k] = 0.f;
}

// ---------------- stage A1: H = relu(edge_attr @ W1 + b1) ----------------
__global__ void __launch_bounds__(128) edge_mlp1_kernel(
    const float* __restrict__ ea, const float* __restrict__ w1,
    const float* __restrict__ b1)
{
    __shared__ float sw[EF * EH];
    __shared__ float sb[EH];
    __shared__ float sea[8 * EF];
    int t = threadIdx.x;
    for (int i = t; i < EF * EH; i += 128) sw[i] = w1[i];
    sb[t] = b1[t];
    int e0 = blockIdx.x * 8;
    for (int i = t; i < 8 * EF; i += 128) {
        int ee = e0 + i / EF;
        if (ee < NE) sea[i] = ea[(size_t)ee * EF + (i % EF)];
    }
    __syncthreads();
    #pragma unroll
    for (int q = 0; q < 8; q++) {
        int e = e0 + q;
        if (e >= NE) break;
        float acc = sb[t];
        #pragma unroll
        for (int i = 0; i < EF; i++) acc += sea[q * EF + i] * sw[i * EH + t];
        g_H[(size_t)e * EH + t] = fmaxf(acc, 0.f);
    }
}

// ---------------- stage A2: We = H @ W2 + b2 (fp32x2, conflict-free LDS) --
// M=ME_PAD, K=128, N=576. Block tile 128x64, 128 threads.
// Microtile 8x8 split 2x(4 rows at ty*4+{0,64}) x 2x(4 cols at tx*4+{0,32}).
// All smem reads are conflict-free LDS.128 (A broadcast over 8 lanes).
__global__ void __launch_bounds__(128) gemm_we_kernel(
    const float* __restrict__ W2, const float* __restrict__ be2)
{
    __shared__ __align__(16) float As[2][16][132];  // [k][m], 528B row (16B mult)
    __shared__ __align__(16) float Bs[2][16][64];   // [k][n], 256B row

    int t  = threadIdx.x;
    int bm = blockIdx.y, bn = blockIdx.x;
    int tx = t & 7;        // 8 col groups
    int ty = t >> 3;       // 16 row groups

    // acc[rb*16 + r*4 + cb*2 + p] : row = rb*64+ty*4+r, cols = cb*32+tx*4+2p..+1
    unsigned long long acc[32];
    #pragma unroll
    for (int i = 0; i < 32; i++) acc[i] = 0ULL;

    const float* Ag = g_H + (size_t)bm * 128 * EH;
    const float* Bg = W2 + bn * 64;

    // stage-invariant load indices
    const int arow0 = t >> 2;          // + 32*p
    const int akq   = (t & 3) * 4;
    const int bkr0  = t >> 4;          // + 8*p
    const int bc4   = (t & 15) * 4;

    float4 ar[4], br[2];

    // ---- prologue: load stage 0 ----
    #pragma unroll
    for (int p = 0; p < 4; p++)
        ar[p] = *reinterpret_cast<const float4*>(Ag + (size_t)(arow0 + 32 * p) * EH + akq);
    #pragma unroll
    for (int p = 0; p < 2; p++)
        br[p] = *reinterpret_cast<const float4*>(Bg + (size_t)(bkr0 + 8 * p) * DW + bc4);
    #pragma unroll
    for (int p = 0; p < 4; p++) {
        int row = arow0 + 32 * p;
        As[0][akq + 0][row] = ar[p].x;
        As[0][akq + 1][row] = ar[p].y;
        As[0][akq + 2][row] = ar[p].z;
        As[0][akq + 3][row] = ar[p].w;
    }
    #pragma unroll
    for (int p = 0; p < 2; p++)
        *reinterpret_cast<float4*>(&Bs[0][bkr0 + 8 * p][bc4]) = br[p];
    __syncthreads();

    #pragma unroll
    for (int s = 0; s < 8; s++) {
        int buf = s & 1;
        // prefetch next stage into registers (overlapped with compute)
        if (s < 7) {
            int kk = (s + 1) * 16;
            #pragma unroll
            for (int p = 0; p < 4; p++)
                ar[p] = *reinterpret_cast<const float4*>(Ag + (size_t)(arow0 + 32 * p) * EH + kk + akq);
            #pragma unroll
            for (int p = 0; p < 2; p++)
                br[p] = *reinterpret_cast<const float4*>(Bg + (size_t)(kk + bkr0 + 8 * p) * DW + bc4);
        }
        // compute on current buffer
        #pragma unroll
        for (int k = 0; k < 16; k++) {
            float4 a0 = *reinterpret_cast<const float4*>(&As[buf][k][ty * 4]);
            float4 a1 = *reinterpret_cast<const float4*>(&As[buf][k][64 + ty * 4]);
            ulonglong2 b0 = *reinterpret_cast<const ulonglong2*>(&Bs[buf][k][tx * 4]);
            ulonglong2 b1 = *reinterpret_cast<const ulonglong2*>(&Bs[buf][k][32 + tx * 4]);

            unsigned long long a2[8];
            asm("mov.b64 %0, {%1, %1};" : "=l"(a2[0]) : "r"(__float_as_uint(a0.x)));
            asm("mov.b64 %0, {%1, %1};" : "=l"(a2[1]) : "r"(__float_as_uint(a0.y)));
            asm("mov.b64 %0, {%1, %1};" : "=l"(a2[2]) : "r"(__float_as_uint(a0.z)));
            asm("mov.b64 %0, {%1, %1};" : "=l"(a2[3]) : "r"(__float_as_uint(a0.w)));
            asm("mov.b64 %0, {%1, %1};" : "=l"(a2[4]) : "r"(__float_as_uint(a1.x)));
            asm("mov.b64 %0, {%1, %1};" : "=l"(a2[5]) : "r"(__float_as_uint(a1.y)));
            asm("mov.b64 %0, {%1, %1};" : "=l"(a2[6]) : "r"(__float_as_uint(a1.z)));
            asm("mov.b64 %0, {%1, %1};" : "=l"(a2[7]) : "r"(__float_as_uint(a1.w)));

            #pragma unroll
            for (int rb = 0; rb < 2; rb++)
                #pragma unroll
                for (int r = 0; r < 4; r++) {
                    unsigned long long av = a2[rb * 4 + r];
                    int base = rb * 16 + r * 4;
                    asm("fma.rn.f32x2 %0, %1, %2, %0;" : "+l"(acc[base + 0]) : "l"(av), "l"(b0.x));
                    asm("fma.rn.f32x2 %0, %1, %2, %0;" : "+l"(acc[base + 1]) : "l"(av), "l"(b0.y));
                    asm("fma.rn.f32x2 %0, %1, %2, %0;" : "+l"(acc[base + 2]) : "l"(av), "l"(b1.x));
                    asm("fma.rn.f32x2 %0, %1, %2, %0;" : "+l"(acc[base + 3]) : "l"(av), "l"(b1.y));
                }
        }
        // store staged registers into the other buffer
        if (s < 7) {
            int nb = buf ^ 1;
            #pragma unroll
            for (int p = 0; p < 4; p++) {
                int row = arow0 + 32 * p;
                As[nb][akq + 0][row] = ar[p].x;
                As[nb][akq + 1][row] = ar[p].y;
                As[nb][akq + 2][row] = ar[p].z;
                As[nb][akq + 3][row] = ar[p].w;
            }
            #pragma unroll
            for (int p = 0; p < 2; p++)
                *reinterpret_cast<float4*>(&Bs[nb][bkr0 + 8 * p][bc4]) = br[p];
            __syncthreads();
        }
    }

    // ---- epilogue ----
    float4 blo = *reinterpret_cast<const float4*>(be2 + bn * 64 + tx * 4);
    float4 bhi = *reinterpret_cast<const float4*>(be2 + bn * 64 + 32 + tx * 4);

    #pragma unroll
    for (int rb = 0; rb < 2; rb++)
        #pragma unroll
        for (int r = 0; r < 4; r++) {
            size_t row = (size_t)bm * 128 + rb * 64 + ty * 4 + r;
            float* dst = g_We + row * DW + bn * 64;
            int base = rb * 16 + r * 4;
            float4 v0, v1;
            v0.x = __uint_as_float((unsigned int)(acc[base + 0] & 0xffffffffULL)) + blo.x;
            v0.y = __uint_as_float((unsigned int)(acc[base + 0] >> 32)) + blo.y;
            v0.z = __uint_as_float((unsigned int)(acc[base + 1] & 0xffffffffULL)) + blo.z;
            v0.w = __uint_as_float((unsigned int)(acc[base + 1] >> 32)) + blo.w;
            v1.x = __uint_as_float((unsigned int)(acc[base + 2] & 0xffffffffULL)) + bhi.x;
            v1.y = __uint_as_float((unsigned int)(acc[base + 2] >> 32)) + bhi.y;
            v1.z = __uint_as_float((unsigned int)(acc[base + 3] & 0xffffffffULL)) + bhi.z;
            v1.w = __uint_as_float((unsigned int)(acc[base + 3] >> 32)) + bhi.w;
            *reinterpret_cast<float4*>(dst + tx * 4) = v0;
            *reinterpret_cast<float4*>(dst + 32 + tx * 4) = v1;
        }
}

// ---------------- graph boundaries from sorted batch (int32) -------------
__global__ void graph_bounds_kernel(const int* __restrict__ batch) {
    int i = blockIdx.x * blockDim.x + threadIdx.x;
    if (i >= NV) return;
    int bi = batch[i];
    if (i == 0) {
        for (int g = 0; g <= bi; g++) g_start[g] = 0;
    } else {
        int bp = batch[i - 1];
        for (int g = bp + 1; g <= bi; g++) g_start[g] = i;
    }
    if (i == NV - 1) {
        for (int g = bi + 1; g <= NB; g++) g_start[g] = NV;
    }
}

// ---------------- message pass: agg[dst] += x[src] @ We[e] ----------------
__global__ void msg_pass_kernel(const float* __restrict__ x,
                                const int* __restrict__ ei, int addCnt)
{
    int w = (blockIdx.x * blockDim.x + threadIdx.x) >> 5;
    int lane = threadIdx.x & 31;
    if (w >= NE) return;
    int src = ei[w];
    int dst = ei[NE + w];
    float xv = (lane < DD) ? x[(size_t)src * DD + lane] : 0.f;
    float acc = 0.f;
    const float* We = g_We + (size_t)w * DW;
    #pragma unroll
    for (int i = 0; i < DD; i++) {
        float xi = __shfl_sync(0xffffffffu, xv, i);
        float wv = (lane < DD) ? We[i * DD + lane] : 0.f;
        acc += xi * wv;
    }
    if (lane < DD) atomicAdd(&g_agg[dst * DD + lane], acc);
    if (addCnt && lane == 0) atomicAdd(&g_cnt[dst], 1.f);
}

// ---------------- node update: agg/cnt + x@root + bias (opt relu) ---------
__global__ void node_update_kernel(const float* __restrict__ xin,
                                   const float* __restrict__ root,
                                   const float* __restrict__ bias,
                                   float* __restrict__ xout, int doRelu)
{
    int idx = blockIdx.x * blockDim.x + threadIdx.x;
    if (idx >= NV * DD) return;
    int v = idx / DD, j = idx % DD;
    float cnt = fmaxf(g_cnt[v], 1.f);
    float acc = g_agg[idx] / cnt + bias[j];
    const float* xr = xin + (size_t)v * DD;
    #pragma unroll
    for (int i = 0; i < DD; i++) acc += xr[i] * root[i * DD + j];
    if (doRelu) acc = fmaxf(acc, 0.f);
    xout[idx] = acc;
}

// ---------------- Set2Set: one full step (LSTM + attention) ---------------
__device__ __forceinline__ float sigm(float v) { return 1.f / (1.f + expf(-v)); }

__global__ void __launch_bounds__(128) s2s_step_kernel(
    const float* __restrict__ x2,
    const float* __restrict__ wih, const float* __restrict__ whh,
    const float* __restrict__ bih, const float* __restrict__ bhh)
{
    __shared__ float sq[2 * DD], shh[DD], scc[DD], sg[4 * DD], hn[DD];
    __shared__ float red[128];
    __shared__ float wr[4][DD];
    __shared__ float ws[4];

    int b = blockIdx.x, t = threadIdx.x;
    if (t < 2 * DD) sq[t] = g_qstar[b * 2 * DD + t];
    if (t < DD) { shh[t] = g_h[b * DD + t]; scc[t] = g_c[b * DD + t]; }
    __syncthreads();

    if (t < 4 * DD) {
        float g = bih[t] + bhh[t];
        #pragma unroll 8
        for (int u = 0; u < 2 * DD; u++) g += sq[u] * wih[t * 2 * DD + u];
        #pragma unroll 8
        for (int u = 0; u < DD; u++) g += shh[u] * whh[t * DD + u];
        sg[t] = g;
    }
    __syncthreads();

    if (t < DD) {
        float ig = sigm(sg[t]);
        float fg = sigm(sg[DD + t]);
        float gg = tanhf(sg[2 * DD + t]);
        float og = sigm(sg[3 * DD + t]);
        float cn = fg * scc[t] + ig * gg;
        float hv = og * tanhf(cn);
        g_c[b * DD + t] = cn;
        g_h[b * DD + t] = hv;
        hn[t] = hv;
    }
    __syncthreads();

    int s0 = g_start[b], s1 = g_start[b + 1];

    float lmax = -3.4e38f;
    for (int n = s0 + t; n < s1; n += 128) {
        const float* xr = x2 + (size_t)n * DD;
        float e = 0.f;
        #pragma unroll
        for (int d = 0; d < DD; d++) e += xr[d] * hn[d];
        lmax = fmaxf(lmax, e);
    }
    red[t] = lmax;
    __syncthreads();
    for (int s = 64; s > 0; s >>= 1) {
        if (t < s) red[t] = fmaxf(red[t], red[t + s]);
        __syncthreads();
    }
    float emax = red[0];
    if (!(emax > -3.0e38f)) emax = 0.f;

    float lsum = 0.f;
    float lr[DD];
    #pragma unroll
    for (int d = 0; d < DD; d++) lr[d] = 0.f;
    for (int n = s0 + t; n < s1; n += 128) {
        const float* xr = x2 + (size_t)n * DD;
        float e = 0.f;
        #pragma unroll
        for (int d = 0; d < DD; d++) e += xr[d] * hn[d];
        float ex = expf(e - emax);
        lsum += ex;
        #pragma unroll
        for (int d = 0; d < DD; d++) lr[d] += ex * xr[d];
    }
    #pragma unroll
    for (int o = 16; o > 0; o >>= 1) {
        lsum += __shfl_xor_sync(0xffffffffu, lsum, o);
        #pragma unroll
        for (int d = 0; d < DD; d++) lr[d] += __shfl_xor_sync(0xffffffffu, lr[d], o);
    }
    int wid = t >> 5, lane = t & 31;
    if (lane == 0) ws[wid] = lsum;
    if (lane < DD) wr[wid][lane] = lr[lane];
    __syncthreads();

    if (t < DD) {
        float denom = ws[0] + ws[1] + ws[2] + ws[3];
        float rsum = wr[0][t] + wr[1][t] + wr[2][t] + wr[3][t];
        float r = rsum / fmaxf(denom, 1e-16f);
        g_qstar[b * 2 * DD + t] = hn[t];
        g_qstar[b * 2 * DD + DD + t] = r;
    }
}

// ---------------- heads ----------------
__global__ void heads_kernel(const float* __restrict__ wfc2, const float* __restrict__ bfc2,
                             const float* __restrict__ wfc3, const float* __restrict__ bfc3,
                             float* __restrict__ out)
{
    int b = blockIdx.x * blockDim.x + threadIdx.x;
    if (b >= NB) return;
    const float* q = g_qstar + b * 2 * DD;
    float hid[8];
    #pragma unroll
    for (int j = 0; j < 8; j++) {
        float h = bfc2[j];
        #pragma unroll 8
        for (int u = 0; u < 2 * DD; u++) h += q[u] * wfc2[u * 8 + j];
        hid[j] = fmaxf(h, 0.f);
    }
    #pragma unroll
    for (int k = 0; k < 2; k++) {
        float o = bfc3[k];
        #pragma unroll
        for (int j = 0; j < 8; j++) o += hid[j] * wfc3[j * 2 + k];
        out[b * 2 + k] = o;
    }
}

// ---------------- launch ----------------
extern "C" void kernel_launch(void* const* d_in, const int* in_sizes, int n_in,
                              void* d_out, int out_size)
{
    const float* x        = (const float*)d_in[0];
    const float* ea       = (const float*)d_in[1];
    const float* w_e1     = (const float*)d_in[2];
    const float* b_e1     = (const float*)d_in[3];
    const float* w_e2     = (const float*)d_in[4];
    const float* b_e2     = (const float*)d_in[5];
    const float* root     = (const float*)d_in[6];
    const float* bias_c   = (const float*)d_in[7];
    const float* w_ih     = (const float*)d_in[8];
    const float* w_hh     = (const float*)d_in[9];
    const float* b_ih     = (const float*)d_in[10];
    const float* b_hh     = (const float*)d_in[11];
    const float* w_fc2    = (const float*)d_in[12];
    const float* b_fc2    = (const float*)d_in[13];
    const float* w_fc3    = (const float*)d_in[14];
    const float* b_fc3    = (const float*)d_in[15];
    const int*   ei       = (const int*)d_in[16];
    const int*   bat      = (const int*)d_in[17];
    float* out            = (float*)d_out;

    float *px1 = nullptr, *px2 = nullptr;
    cudaGetSymbolAddress((void**)&px1, g_x1);
    cudaGetSymbolAddress((void**)&px2, g_x2);

    // order chosen so the big GEMM sits in the ncu-captured launch slot
    zero_all_kernel<<<1024, 256>>>();
    edge_mlp1_kernel<<<NE / 8, 128>>>(ea, w_e1, b_e1);
    graph_bounds_kernel<<<(NV + 255) / 256, 256>>>(bat);
    {
        dim3 grid(NT, MT);   // 9 x 1563
        gemm_we_kernel<<<grid, 128>>>(w_e2, b_e2);
    }

    // NNConv layer 1 (input x, relu -> g_x1)
    msg_pass_kernel<<<NE / 8, 256>>>(x, ei, 1);
    node_update_kernel<<<(NV * DD + 255) / 256, 256>>>(x, root, bias_c, px1, 1);

    // NNConv layer 2 (input g_x1 -> g_x2)
    zero_agg_kernel<<<512, 256>>>();
    msg_pass_kernel<<<NE / 8, 256>>>(px1, ei, 0);
    node_update_kernel<<<(NV * DD + 255) / 256, 256>>>(px1, root, bias_c, px2, 0);

    // Set2Set: 3 steps
    for (int s = 0; s < 3; s++)
        s2s_step_kernel<<<NB, 128>>>(px2, w_ih, w_hh, b_ih, b_hh);

    heads_kernel<<<(NB + 255) / 256, 256>>>(w_fc2, b_fc2, w_fc3, b_fc3, out);
}

// round 12
// speedup vs baseline: 1.5998x; 1.1551x over previous
#include <cuda_runtime.h>
#include <cuda_bf16.h>
#include <cstdint>

// ---------------- problem constants ----------------
#define NV      50000      // nodes
#define NE      200000     // edges
#define NB      1024       // graphs
#define DD      24         // node feature dim
#define EF      8          // edge feature dim
#define EH      128        // edge MLP hidden
#define DW      576        // D*D
#define MT      1563       // m-tiles of 128 edges
#define ME_PAD  (MT*128)   // 200064 padded edge rows
#define NT      9          // n-tiles of 64 over DW=576

// ---------------- device scratch (zero-init at module load) ----------------
__device__ __align__(16) __nv_bfloat16 g_Hhi[(size_t)ME_PAD * EH];  // 51.2 MB
__device__ __align__(16) __nv_bfloat16 g_Hlo[(size_t)ME_PAD * EH];  // 51.2 MB
__device__ __align__(16) __nv_bfloat16 g_Bhi[EH * DW];              // 144 KB
__device__ __align__(16) __nv_bfloat16 g_Blo[EH * DW];              // 144 KB
__device__ float g_We[(size_t)ME_PAD * DW];    // 461 MB per-edge 24x24 weights
__device__ float g_agg[NV * DD];
__device__ float g_cnt[NV];
__device__ float g_x1[NV * DD];
__device__ float g_x2[NV * DD];
__device__ int   g_start[NB + 1];
__device__ float g_qstar[NB * 2 * DD];
__device__ float g_h[NB * DD];
__device__ float g_c[NB * DD];

// ---------------- zero + W2 bf16-split conversion (fused) ----------------
__global__ void zero_all_kernel(const float* __restrict__ w_e2) {
    int i = blockIdx.x * blockDim.x + threadIdx.x;
    int stride = gridDim.x * blockDim.x;
    for (int k = i; k < NV * DD; k += stride) g_agg[k] = 0.f;
    for (int k = i; k < NV; k += stride) g_cnt[k] = 0.f;
    for (int k = i; k < NB * 2 * DD; k += stride) g_qstar[k] = 0.f;
    for (int k = i; k < NB * DD; k += stride) { g_h[k] = 0.f; g_c[k] = 0.f; }
    for (int k = i; k < EH * DW; k += stride) {
        float v = w_e2[k];
        __nv_bfloat16 hi = __float2bfloat16(v);
        g_Bhi[k] = hi;
        g_Blo[k] = __float2bfloat16(v - __bfloat162float(hi));
    }
}
__global__ void zero_agg_kernel() {
    int i = blockIdx.x * blockDim.x + threadIdx.x;
    int stride = gridDim.x * blockDim.x;
    for (int k = i; k < NV * DD; k += stride) g_agg[k] = 0.f;
}

// ---------------- stage A1: H = relu(ea@W1+b1) -> bf16 hi/lo --------------
__global__ void __launch_bounds__(128) edge_mlp1_kernel(
    const float* __restrict__ ea, const float* __restrict__ w1,
    const float* __restrict__ b1)
{
    __shared__ float sw[EF * EH];
    __shared__ float sb[EH];
    __shared__ float sea[8 * EF];
    int t = threadIdx.x;
    for (int i = t; i < EF * EH; i += 128) sw[i] = w1[i];
    sb[t] = b1[t];
    int e0 = blockIdx.x * 8;
    for (int i = t; i < 8 * EF; i += 128) {
        int ee = e0 + i / EF;
        if (ee < NE) sea[i] = ea[(size_t)ee * EF + (i % EF)];
    }
    __syncthreads();
    #pragma unroll
    for (int q = 0; q < 8; q++) {
        int e = e0 + q;
        if (e >= NE) break;
        float acc = sb[t];
        #pragma unroll
        for (int i = 0; i < EF; i++) acc += sea[q * EF + i] * sw[i * EH + t];
        acc = fmaxf(acc, 0.f);
        __nv_bfloat16 hi = __float2bfloat16(acc);
        g_Hhi[(size_t)e * EH + t] = hi;
        g_Hlo[(size_t)e * EH + t] = __float2bfloat16(acc - __bfloat162float(hi));
    }
}

// ---------------- stage A2: We = H @ W2 + b2  (mma.sync bf16 split) -------
// CTA: 128(M) x 64(N) x K128, 256 threads, 8 warps (4m x 2n) of 32x32.
// K staged 32 at a time via cp.async into 8x8-tiled smem; double buffered.
// smem per stage: A hi 8K + A lo 8K + B hi 4K + B lo 4K = 24K; x2 = 48K.
#define STG_SZ   24576
#define OFF_AHI  0
#define OFF_ALO  8192
#define OFF_BHI  16384
#define OFF_BLO  20480

__device__ __forceinline__ uint32_t smem_u32(const void* p) {
    uint32_t a;
    asm("{ .reg .u64 t; cvta.to.shared.u64 t, %1; cvt.u32.u64 %0, t; }" : "=r"(a) : "l"(p));
    return a;
}
#define CPA16(dst, src) \
    asm volatile("cp.async.cg.shared.global [%0], [%1], 16;" :: "r"(dst), "l"(src) : "memory")
#define CPA_COMMIT() asm volatile("cp.async.commit_group;" ::: "memory")
#define CPA_WAIT(n)  asm volatile("cp.async.wait_group %0;" :: "n"(n) : "memory")

#define LDSM4(r, addr) \
    asm volatile("ldmatrix.sync.aligned.m8n8.x4.shared.b16 {%0,%1,%2,%3}, [%4];" \
        : "=r"((r)[0]), "=r"((r)[1]), "=r"((r)[2]), "=r"((r)[3]) : "r"(addr))
#define LDSM4T(r, addr) \
    asm volatile("ldmatrix.sync.aligned.m8n8.x4.trans.shared.b16 {%0,%1,%2,%3}, [%4];" \
        : "=r"((r)[0]), "=r"((r)[1]), "=r"((r)[2]), "=r"((r)[3]) : "r"(addr))
#define MMA16816(d, a, b0, b1) \
    asm volatile("mma.sync.aligned.m16n8k16.row.col.f32.bf16.bf16.f32 " \
        "{%0,%1,%2,%3}, {%4,%5,%6,%7}, {%8,%9}, {%0,%1,%2,%3};" \
        : "+f"((d)[0]), "+f"((d)[1]), "+f"((d)[2]), "+f"((d)[3]) \
        : "r"((a)[0]), "r"((a)[1]), "r"((a)[2]), "r"((a)[3]), "r"(b0), "r"(b1))

__global__ void __launch_bounds__(256) gemm_we_kernel(
    const float* __restrict__ be2)
{
    __shared__ __align__(16) char smem[2 * STG_SZ];
    uint32_t sb = smem_u32(smem);

    int t = threadIdx.x;
    int lane = t & 31, wid = t >> 5;
    int warp_m = wid & 3, warp_n = wid >> 2;
    int bn = blockIdx.x, bm = blockIdx.y;

    float acc[2][4][4];
    #pragma unroll
    for (int f = 0; f < 2; f++)
        #pragma unroll
        for (int g = 0; g < 4; g++)
            #pragma unroll
            for (int i = 0; i < 4; i++) acc[f][g][i] = 0.f;

    // staging indices (stage-invariant)
    const int amb = t >> 5;              // c = t + p*256 -> mb = c>>5 (p adds 8)
    const int akb = (t >> 3) & 3;
    const int am8 = t & 7;
    const int bkb = t >> 6;
    const int bnb = (t >> 3) & 7;
    const int bk8 = t & 7;

    const char* HhiB = (const char*)g_Hhi;
    const char* HloB = (const char*)g_Hlo;
    const char* BhiB = (const char*)g_Bhi;
    const char* BloB = (const char*)g_Blo;

    // ---- stage loader (6 cp.async of 16B per thread) ----
    #define STAGE_LOAD(s) do {                                                  \
        int _buf = (s) & 1; int _k0 = (s) * 32;                                 \
        uint32_t _base = sb + _buf * STG_SZ;                                    \
        _Pragma("unroll")                                                       \
        for (int p = 0; p < 2; p++) {                                           \
            int c = t + p * 256;                                                \
            int mb = amb + p * 8;                                               \
            size_t e = (size_t)bm * 128 + mb * 8 + am8;                         \
            size_t so = (e * EH + _k0 + akb * 8) * 2;                           \
            CPA16(_base + OFF_AHI + c * 16, HhiB + so);                         \
            CPA16(_base + OFF_ALO + c * 16, HloB + so);                         \
        }                                                                       \
        {                                                                       \
            size_t k = (size_t)_k0 + bkb * 8 + bk8;                             \
            size_t so = (k * DW + bn * 64 + bnb * 8) * 2;                       \
            CPA16(_base + OFF_BHI + t * 16, BhiB + so);                         \
            CPA16(_base + OFF_BLO + t * 16, BloB + so);                         \
        }                                                                       \
        CPA_COMMIT();                                                           \
    } while (0)

    STAGE_LOAD(0);

    #pragma unroll
    for (int s = 0; s < 4; s++) {
        if (s < 3) STAGE_LOAD(s + 1);
        if (s < 3) { CPA_WAIT(1); } else { CPA_WAIT(0); }
        __syncthreads();

        uint32_t base = sb + (s & 1) * STG_SZ;
        #pragma unroll
        for (int ks = 0; ks < 2; ks++) {
            uint32_t ahi[2][4], alo[2][4], bhi[2][4], blo[2][4];
            #pragma unroll
            for (int f = 0; f < 2; f++) {
                int mb = warp_m * 4 + f * 2 + ((lane >> 3) & 1);
                int kb = ks * 2 + ((lane >> 4) & 1);
                uint32_t off = (uint32_t)(((mb * 4 + kb) * 8 + (lane & 7)) * 16);
                LDSM4(ahi[f], base + OFF_AHI + off);
                LDSM4(alo[f], base + OFF_ALO + off);
            }
            #pragma unroll
            for (int g2 = 0; g2 < 2; g2++) {
                int kb = ks * 2 + ((lane >> 3) & 1);
                int nb = warp_n * 4 + g2 * 2 + ((lane >> 4) & 1);
                uint32_t off = (uint32_t)(((kb * 8 + nb) * 8 + (lane & 7)) * 16);
                LDSM4T(bhi[g2], base + OFF_BHI + off);
                LDSM4T(blo[g2], base + OFF_BLO + off);
            }
            #pragma unroll
            for (int f = 0; f < 2; f++)
                #pragma unroll
                for (int g = 0; g < 4; g++) {
                    uint32_t bh0 = bhi[g >> 1][(g & 1) * 2];
                    uint32_t bh1 = bhi[g >> 1][(g & 1) * 2 + 1];
                    uint32_t bl0 = blo[g >> 1][(g & 1) * 2];
                    uint32_t bl1 = blo[g >> 1][(g & 1) * 2 + 1];
                    MMA16816(acc[f][g], ahi[f], bh0, bh1);   // hi*hi
                    MMA16816(acc[f][g], alo[f], bh0, bh1);   // lo*hi
                    MMA16816(acc[f][g], ahi[f], bl0, bl1);   // hi*lo
                }
        }
        if (s < 3) __syncthreads();
    }

    // ---- epilogue: add bias, store fp32 ----
    int r0 = lane >> 2, c0 = (lane & 3) * 2;
    #pragma unroll
    for (int g = 0; g < 4; g++) {
        int col = bn * 64 + warp_n * 32 + g * 8 + c0;
        float bx = be2[col], by = be2[col + 1];
        #pragma unroll
        for (int f = 0; f < 2; f++) {
            size_t row = (size_t)bm * 128 + warp_m * 32 + f * 16 + r0;
            float2 v0 = make_float2(acc[f][g][0] + bx, acc[f][g][1] + by);
            float2 v1 = make_float2(acc[f][g][2] + bx, acc[f][g][3] + by);
            *reinterpret_cast<float2*>(&g_We[row * DW + col]) = v0;
            *reinterpret_cast<float2*>(&g_We[(row + 8) * DW + col]) = v1;
        }
    }
}

// ---------------- graph boundaries from sorted batch (int32) -------------
__global__ void graph_bounds_kernel(const int* __restrict__ batch) {
    int i = blockIdx.x * blockDim.x + threadIdx.x;
    if (i >= NV) return;
    int bi = batch[i];
    if (i == 0) {
        for (int g = 0; g <= bi; g++) g_start[g] = 0;
    } else {
        int bp = batch[i - 1];
        for (int g = bp + 1; g <= bi; g++) g_start[g] = i;
    }
    if (i == NV - 1) {
        for (int g = bi + 1; g <= NB; g++) g_start[g] = NV;
    }
}

// ---------------- message pass: agg[dst] += x[src] @ We[e] ----------------
__global__ void msg_pass_kernel(const float* __restrict__ x,
                                const int* __restrict__ ei, int addCnt)
{
    int w = (blockIdx.x * blockDim.x + threadIdx.x) >> 5;
    int lane = threadIdx.x & 31;
    if (w >= NE) return;
    int src = ei[w];
    int dst = ei[NE + w];
    float xv = (lane < DD) ? x[(size_t)src * DD + lane] : 0.f;
    float acc = 0.f;
    const float* We = g_We + (size_t)w * DW;
    #pragma unroll
    for (int i = 0; i < DD; i++) {
        float xi = __shfl_sync(0xffffffffu, xv, i);
        float wv = (lane < DD) ? We[i * DD + lane] : 0.f;
        acc += xi * wv;
    }
    if (lane < DD) atomicAdd(&g_agg[dst * DD + lane], acc);
    if (addCnt && lane == 0) atomicAdd(&g_cnt[dst], 1.f);
}

// ---------------- node update: agg/cnt + x@root + bias (opt relu) ---------
__global__ void node_update_kernel(const float* __restrict__ xin,
                                   const float* __restrict__ root,
                                   const float* __restrict__ bias,
                                   float* __restrict__ xout, int doRelu)
{
    int idx = blockIdx.x * blockDim.x + threadIdx.x;
    if (idx >= NV * DD) return;
    int v = idx / DD, j = idx % DD;
    float cnt = fmaxf(g_cnt[v], 1.f);
    float acc = g_agg[idx] / cnt + bias[j];
    const float* xr = xin + (size_t)v * DD;
    #pragma unroll
    for (int i = 0; i < DD; i++) acc += xr[i] * root[i * DD + j];
    if (doRelu) acc = fmaxf(acc, 0.f);
    xout[idx] = acc;
}

// ---------------- Set2Set: one full step (LSTM + attention) ---------------
__device__ __forceinline__ float sigm(float v) { return 1.f / (1.f + expf(-v)); }

__global__ void __launch_bounds__(128) s2s_step_kernel(
    const float* __restrict__ x2,
    const float* __restrict__ wih, const float* __restrict__ whh,
    const float* __restrict__ bih, const float* __restrict__ bhh)
{
    __shared__ float sq[2 * DD], shh[DD], scc[DD], sg[4 * DD], hn[DD];
    __shared__ float red[128];
    __shared__ float wr[4][DD];
    __shared__ float ws[4];

    int b = blockIdx.x, t = threadIdx.x;
    if (t < 2 * DD) sq[t] = g_qstar[b * 2 * DD + t];
    if (t < DD) { shh[t] = g_h[b * DD + t]; scc[t] = g_c[b * DD + t]; }
    __syncthreads();

    if (t < 4 * DD) {
        float g = bih[t] + bhh[t];
        #pragma unroll 8
        for (int u = 0; u < 2 * DD; u++) g += sq[u] * wih[t * 2 * DD + u];
        #pragma unroll 8
        for (int u = 0; u < DD; u++) g += shh[u] * whh[t * DD + u];
        sg[t] = g;
    }
    __syncthreads();

    if (t < DD) {
        float ig = sigm(sg[t]);
        float fg = sigm(sg[DD + t]);
        float gg = tanhf(sg[2 * DD + t]);
        float og = sigm(sg[3 * DD + t]);
        float cn = fg * scc[t] + ig * gg;
        float hv = og * tanhf(cn);
        g_c[b * DD + t] = cn;
        g_h[b * DD + t] = hv;
        hn[t] = hv;
    }
    __syncthreads();

    int s0 = g_start[b], s1 = g_start[b + 1];

    float lmax = -3.4e38f;
    for (int n = s0 + t; n < s1; n += 128) {
        const float* xr = x2 + (size_t)n * DD;
        float e = 0.f;
        #pragma unroll
        for (int d = 0; d < DD; d++) e += xr[d] * hn[d];
        lmax = fmaxf(lmax, e);
    }
    red[t] = lmax;
    __syncthreads();
    for (int s = 64; s > 0; s >>= 1) {
        if (t < s) red[t] = fmaxf(red[t], red[t + s]);
        __syncthreads();
    }
    float emax = red[0];
    if (!(emax > -3.0e38f)) emax = 0.f;

    float lsum = 0.f;
    float lr[DD];
    #pragma unroll
    for (int d = 0; d < DD; d++) lr[d] = 0.f;
    for (int n = s0 + t; n < s1; n += 128) {
        const float* xr = x2 + (size_t)n * DD;
        float e = 0.f;
        #pragma unroll
        for (int d = 0; d < DD; d++) e += xr[d] * hn[d];
        float ex = expf(e - emax);
        lsum += ex;
        #pragma unroll
        for (int d = 0; d < DD; d++) lr[d] += ex * xr[d];
    }
    #pragma unroll
    for (int o = 16; o > 0; o >>= 1) {
        lsum += __shfl_xor_sync(0xffffffffu, lsum, o);
        #pragma unroll
        for (int d = 0; d < DD; d++) lr[d] += __shfl_xor_sync(0xffffffffu, lr[d], o);
    }
    int wid = t >> 5, lane = t & 31;
    if (lane == 0) ws[wid] = lsum;
    if (lane < DD) wr[wid][lane] = lr[lane];
    __syncthreads();

    if (t < DD) {
        float denom = ws[0] + ws[1] + ws[2] + ws[3];
        float rsum = wr[0][t] + wr[1][t] + wr[2][t] + wr[3][t];
        float r = rsum / fmaxf(denom, 1e-16f);
        g_qstar[b * 2 * DD + t] = hn[t];
        g_qstar[b * 2 * DD + DD + t] = r;
    }
}

// ---------------- heads ----------------
__global__ void heads_kernel(const float* __restrict__ wfc2, const float* __restrict__ bfc2,
                             const float* __restrict__ wfc3, const float* __restrict__ bfc3,
                             float* __restrict__ out)
{
    int b = blockIdx.x * blockDim.x + threadIdx.x;
    if (b >= NB) return;
    const float* q = g_qstar + b * 2 * DD;
    float hid[8];
    #pragma unroll
    for (int j = 0; j < 8; j++) {
        float h = bfc2[j];
        #pragma unroll 8
        for (int u = 0; u < 2 * DD; u++) h += q[u] * wfc2[u * 8 + j];
        hid[j] = fmaxf(h, 0.f);
    }
    #pragma unroll
    for (int k = 0; k < 2; k++) {
        float o = bfc3[k];
        #pragma unroll
        for (int j = 0; j < 8; j++) o += hid[j] * wfc3[j * 2 + k];
        out[b * 2 + k] = o;
    }
}

// ---------------- launch ----------------
extern "C" void kernel_launch(void* const* d_in, const int* in_sizes, int n_in,
                              void* d_out, int out_size)
{
    const float* x        = (const float*)d_in[0];
    const float* ea       = (const float*)d_in[1];
    const float* w_e1     = (const float*)d_in[2];
    const float* b_e1     = (const float*)d_in[3];
    const float* w_e2     = (const float*)d_in[4];
    const float* b_e2     = (const float*)d_in[5];
    const float* root     = (const float*)d_in[6];
    const float* bias_c   = (const float*)d_in[7];
    const float* w_ih     = (const float*)d_in[8];
    const float* w_hh     = (const float*)d_in[9];
    const float* b_ih     = (const float*)d_in[10];
    const float* b_hh     = (const float*)d_in[11];
    const float* w_fc2    = (const float*)d_in[12];
    const float* b_fc2    = (const float*)d_in[13];
    const float* w_fc3    = (const float*)d_in[14];
    const float* b_fc3    = (const float*)d_in[15];
    const int*   ei       = (const int*)d_in[16];
    const int*   bat      = (const int*)d_in[17];
    float* out            = (float*)d_out;

    float *px1 = nullptr, *px2 = nullptr;
    cudaGetSymbolAddress((void**)&px1, g_x1);
    cudaGetSymbolAddress((void**)&px2, g_x2);

    zero_all_kernel<<<1024, 256>>>(w_e2);          // also converts W2 -> bf16 hi/lo
    edge_mlp1_kernel<<<NE / 8, 128>>>(ea, w_e1, b_e1);
    graph_bounds_kernel<<<(NV + 255) / 256, 256>>>(bat);
    {
        dim3 grid(NT, MT);   // 9 x 1563
        gemm_we_kernel<<<grid, 256>>>(b_e2);
    }

    // NNConv layer 1 (input x, relu -> g_x1)
    msg_pass_kernel<<<NE / 8, 256>>>(x, ei, 1);
    node_update_kernel<<<(NV * DD + 255) / 256, 256>>>(x, root, bias_c, px1, 1);

    // NNConv layer 2 (input g_x1 -> g_x2)
    zero_agg_kernel<<<512, 256>>>();
    msg_pass_kernel<<<NE / 8, 256>>>(px1, ei, 0);
    node_update_kernel<<<(NV * DD + 255) / 256, 256>>>(px1, root, bias_c, px2, 0);

    // Set2Set: 3 steps
    for (int s = 0; s < 3; s++)
        s2s_step_kernel<<<NB, 128>>>(px2, w_ih, w_hh, b_ih, b_hh);

    heads_kernel<<<(NB + 255) / 256, 256>>>(w_fc2, b_fc2, w_fc3, b_fc3, out);
}

// round 14
// speedup vs baseline: 1.6262x; 1.0165x over previous
#include <cuda_runtime.h>
#include <cuda_bf16.h>
#include <cstdint>

// ---------------- problem constants ----------------
#define NV      50000      // nodes
#define NE      200000     // edges
#define NB      1024       // graphs
#define DD      24         // node feature dim
#define EF      8          // edge feature dim
#define EH      128        // edge MLP hidden
#define DW      576        // D*D
#define MT      1563       // m-tiles of 128 edges
#define ME_PAD  (MT*128)   // 200064 padded edge rows
#define BN      192        // n per CTA
#define NTC     3          // n-tiles of 192 over DW=576

// ---------------- device scratch (zero-init at module load) ----------------
__device__ __align__(16) __nv_bfloat16 g_Hhi[(size_t)ME_PAD * EH];  // 51.2 MB
__device__ __align__(16) __nv_bfloat16 g_Hlo[(size_t)ME_PAD * EH];  // 51.2 MB
__device__ __align__(16) __nv_bfloat16 g_Bhi[EH * DW];              // 144 KB
__device__ __align__(16) __nv_bfloat16 g_Blo[EH * DW];              // 144 KB
__device__ float g_We[(size_t)ME_PAD * DW];    // 461 MB per-edge 24x24 weights
__device__ float g_agg[NV * DD];
__device__ float g_cnt[NV];
__device__ float g_x1[NV * DD];
__device__ float g_x2[NV * DD];
__device__ int   g_start[NB + 1];
__device__ float g_qstar[NB * 2 * DD];
__device__ float g_h[NB * DD];
__device__ float g_c[NB * DD];

// ---------------- zero + W2 bf16-split conversion (fused) ----------------
__global__ void zero_all_kernel(const float* __restrict__ w_e2) {
    int i = blockIdx.x * blockDim.x + threadIdx.x;
    int stride = gridDim.x * blockDim.x;
    for (int k = i; k < NV * DD; k += stride) g_agg[k] = 0.f;
    for (int k = i; k < NV; k += stride) g_cnt[k] = 0.f;
    for (int k = i; k < NB * 2 * DD; k += stride) g_qstar[k] = 0.f;
    for (int k = i; k < NB * DD; k += stride) { g_h[k] = 0.f; g_c[k] = 0.f; }
    for (int k = i; k < EH * DW; k += stride) {
        float v = w_e2[k];
        __nv_bfloat16 hi = __float2bfloat16(v);
        g_Bhi[k] = hi;
        g_Blo[k] = __float2bfloat16(v - __bfloat162float(hi));
    }
}
__global__ void zero_agg_kernel() {
    int i = blockIdx.x * blockDim.x + threadIdx.x;
    int stride = gridDim.x * blockDim.x;
    for (int k = i; k < NV * DD; k += stride) g_agg[k] = 0.f;
}

// ---------------- stage A1: H = relu(ea@W1+b1) -> bf16 hi/lo --------------
__global__ void __launch_bounds__(128) edge_mlp1_kernel(
    const float* __restrict__ ea, const float* __restrict__ w1,
    const float* __restrict__ b1)
{
    __shared__ float sw[EF * EH];
    __shared__ float sb[EH];
    __shared__ float sea[8 * EF];
    int t = threadIdx.x;
    for (int i = t; i < EF * EH; i += 128) sw[i] = w1[i];
    sb[t] = b1[t];
    int e0 = blockIdx.x * 8;
    for (int i = t; i < 8 * EF; i += 128) {
        int ee = e0 + i / EF;
        if (ee < NE) sea[i] = ea[(size_t)ee * EF + (i % EF)];
    }
    __syncthreads();
    #pragma unroll
    for (int q = 0; q < 8; q++) {
        int e = e0 + q;
        if (e >= NE) break;
        float acc = sb[t];
        #pragma unroll
        for (int i = 0; i < EF; i++) acc += sea[q * EF + i] * sw[i * EH + t];
        acc = fmaxf(acc, 0.f);
        __nv_bfloat16 hi = __float2bfloat16(acc);
        g_Hhi[(size_t)e * EH + t] = hi;
        g_Hlo[(size_t)e * EH + t] = __float2bfloat16(acc - __bfloat162float(hi));
    }
}

// ---------------- stage A2: We = H @ W2 + b2  (mma.sync bf16 split) -------
// CTA: 128(M) x 192(N) x K128, 256 threads, 8 warps (4m x 2n), warp 32x96.
// Entire K prefetched: 4 cp.async stages committed up front (160KB smem),
// consumed with progressive wait_group. A read once per 192 cols (3x less L2).
#define STG_SZ   40960
#define OFF_AHI  0
#define OFF_ALO  8192
#define OFF_BHI  16384
#define OFF_BLO  28672

__device__ __forceinline__ uint32_t smem_u32(const void* p) {
    uint32_t a;
    asm("{ .reg .u64 t; cvta.to.shared.u64 t, %1; cvt.u32.u64 %0, t; }" : "=r"(a) : "l"(p));
    return a;
}
#define CPA16(dst, src) \
    asm volatile("cp.async.cg.shared.global [%0], [%1], 16;" :: "r"(dst), "l"(src) : "memory")
#define CPA_COMMIT() asm volatile("cp.async.commit_group;" ::: "memory")
#define CPA_WAIT(n)  asm volatile("cp.async.wait_group %0;" :: "n"(n) : "memory")

#define LDSM4(r, addr) \
    asm volatile("ldmatrix.sync.aligned.m8n8.x4.shared.b16 {%0,%1,%2,%3}, [%4];" \
        : "=r"((r)[0]), "=r"((r)[1]), "=r"((r)[2]), "=r"((r)[3]) : "r"(addr))
#define LDSM4T(r, addr) \
    asm volatile("ldmatrix.sync.aligned.m8n8.x4.trans.shared.b16 {%0,%1,%2,%3}, [%4];" \
        : "=r"((r)[0]), "=r"((r)[1]), "=r"((r)[2]), "=r"((r)[3]) : "r"(addr))
#define MMA16816(d, a, b0, b1) \
    asm volatile("mma.sync.aligned.m16n8k16.row.col.f32.bf16.bf16.f32 " \
        "{%0,%1,%2,%3}, {%4,%5,%6,%7}, {%8,%9}, {%0,%1,%2,%3};" \
        : "+f"((d)[0]), "+f"((d)[1]), "+f"((d)[2]), "+f"((d)[3]) \
        : "r"((a)[0]), "r"((a)[1]), "r"((a)[2]), "r"((a)[3]), "r"(b0), "r"(b1))

__global__ void __launch_bounds__(256, 1) gemm_we_kernel(
    const float* __restrict__ be2)
{
    extern __shared__ __align__(16) char smem[];
    uint32_t sb = smem_u32(smem);

    int t = threadIdx.x;
    int lane = t & 31, wid = t >> 5;
    int warp_m = wid & 3, warp_n = wid >> 2;
    int bn = blockIdx.x, bm = blockIdx.y;

    float acc[2][12][4];
    #pragma unroll
    for (int f = 0; f < 2; f++)
        #pragma unroll
        for (int g = 0; g < 12; g++)
            #pragma unroll
            for (int i = 0; i < 4; i++) acc[f][g][i] = 0.f;

    // staging indices (stage-invariant)
    const int amb = t >> 5;              // + p*8
    const int akb = (t >> 3) & 3;
    const int am8 = t & 7;

    const char* HhiB = (const char*)g_Hhi;
    const char* HloB = (const char*)g_Hlo;
    const char* BhiB = (const char*)g_Bhi;
    const char* BloB = (const char*)g_Blo;

    // ---- issue all 4 K-stages up front ----
    #pragma unroll
    for (int s = 0; s < 4; s++) {
        int k0 = s * 32;
        uint32_t base = sb + s * STG_SZ;
        // A: 512 x 16B per matrix, 2 per thread
        #pragma unroll
        for (int p = 0; p < 2; p++) {
            int c = t + p * 256;
            int mb = amb + p * 8;
            size_t e = (size_t)bm * 128 + mb * 8 + am8;
            size_t so = (e * EH + k0 + akb * 8) * 2;
            CPA16(base + OFF_AHI + c * 16, HhiB + so);
            CPA16(base + OFF_ALO + c * 16, HloB + so);
        }
        // B: 768 x 16B per matrix, 3 per thread; block (kb,nb) at ((kb*24+nb)*8+k8)*16
        #pragma unroll
        for (int p = 0; p < 3; p++) {
            int c = t + p * 256;
            int kb = c / 192;
            int rem = c - kb * 192;
            int nb = rem >> 3, k8 = rem & 7;
            size_t k = (size_t)k0 + kb * 8 + k8;
            size_t so = (k * DW + bn * BN + nb * 8) * 2;
            uint32_t doff = (uint32_t)(((kb * 24 + nb) * 8 + k8) * 16);
            CPA16(base + OFF_BHI + doff, BhiB + so);
            CPA16(base + OFF_BLO + doff, BloB + so);
        }
        CPA_COMMIT();
    }

    // ---- consume stages with progressive waits ----
    #pragma unroll
    for (int s = 0; s < 4; s++) {
        if (s == 0) { CPA_WAIT(3); }
        else if (s == 1) { CPA_WAIT(2); }
        else if (s == 2) { CPA_WAIT(1); }
        else { CPA_WAIT(0); }
        __syncthreads();

        uint32_t base = sb + s * STG_SZ;
        #pragma unroll
        for (int ks = 0; ks < 2; ks++) {
            uint32_t ahi[2][4], alo[2][4];
            #pragma unroll
            for (int f = 0; f < 2; f++) {
                int mb = warp_m * 4 + f * 2 + ((lane >> 3) & 1);
                int kb = ks * 2 + ((lane >> 4) & 1);
                uint32_t off = (uint32_t)(((mb * 4 + kb) * 8 + (lane & 7)) * 16);
                LDSM4(ahi[f], base + OFF_AHI + off);
                LDSM4(alo[f], base + OFF_ALO + off);
            }
            #pragma unroll
            for (int g2 = 0; g2 < 6; g2++) {
                uint32_t bhi[4], blo[4];
                int kb = ks * 2 + ((lane >> 3) & 1);
                int nb = warp_n * 12 + g2 * 2 + ((lane >> 4) & 1);
                uint32_t off = (uint32_t)(((kb * 24 + nb) * 8 + (lane & 7)) * 16);
                LDSM4T(bhi, base + OFF_BHI + off);
                LDSM4T(blo, base + OFF_BLO + off);
                #pragma unroll
                for (int f = 0; f < 2; f++)
                    #pragma unroll
                    for (int gg = 0; gg < 2; gg++) {
                        float* a4 = acc[f][g2 * 2 + gg];
                        MMA16816(a4, ahi[f], bhi[gg * 2], bhi[gg * 2 + 1]);  // hi*hi
                        MMA16816(a4, alo[f], bhi[gg * 2], bhi[gg * 2 + 1]);  // lo*hi
                        MMA16816(a4, ahi[f], blo[gg * 2], blo[gg * 2 + 1]);  // hi*lo
                    }
            }
        }
    }

    // ---- epilogue: add bias, store fp32 ----
    int r0 = lane >> 2, c0 = (lane & 3) * 2;
    #pragma unroll
    for (int g = 0; g < 12; g++) {
        int col = bn * BN + warp_n * 96 + g * 8 + c0;
        float bx = be2[col], by = be2[col + 1];
        #pragma unroll
        for (int f = 0; f < 2; f++) {
            size_t row = (size_t)bm * 128 + warp_m * 32 + f * 16 + r0;
            float2 v0 = make_float2(acc[f][g][0] + bx, acc[f][g][1] + by);
            float2 v1 = make_float2(acc[f][g][2] + bx, acc[f][g][3] + by);
            *reinterpret_cast<float2*>(&g_We[row * DW + col]) = v0;
            *reinterpret_cast<float2*>(&g_We[(row + 8) * DW + col]) = v1;
        }
    }
}

// ---------------- graph boundaries from sorted batch (int32) -------------
__global__ void graph_bounds_kernel(const int* __restrict__ batch) {
    int i = blockIdx.x * blockDim.x + threadIdx.x;
    if (i >= NV) return;
    int bi = batch[i];
    if (i == 0) {
        for (int g = 0; g <= bi; g++) g_start[g] = 0;
    } else {
        int bp = batch[i - 1];
        for (int g = bp + 1; g <= bi; g++) g_start[g] = i;
    }
    if (i == NV - 1) {
        for (int g = bi + 1; g <= NB; g++) g_start[g] = NV;
    }
}

// ---------------- message pass: agg[dst] += x[src] @ We[e] ----------------
__global__ void msg_pass_kernel(const float* __restrict__ x,
                                const int* __restrict__ ei, int addCnt)
{
    int w = (blockIdx.x * blockDim.x + threadIdx.x) >> 5;
    int lane = threadIdx.x & 31;
    if (w >= NE) return;
    int src = ei[w];
    int dst = ei[NE + w];
    float xv = (lane < DD) ? x[(size_t)src * DD + lane] : 0.f;
    float acc = 0.f;
    const float* We = g_We + (size_t)w * DW;
    #pragma unroll
    for (int i = 0; i < DD; i++) {
        float xi = __shfl_sync(0xffffffffu, xv, i);
        float wv = (lane < DD) ? We[i * DD + lane] : 0.f;
        acc += xi * wv;
    }
    if (lane < DD) atomicAdd(&g_agg[dst * DD + lane], acc);
    if (addCnt && lane == 0) atomicAdd(&g_cnt[dst], 1.f);
}

// ---------------- node update: agg/cnt + x@root + bias (opt relu) ---------
__global__ void node_update_kernel(const float* __restrict__ xin,
                                   const float* __restrict__ root,
                                   const float* __restrict__ bias,
                                   float* __restrict__ xout, int doRelu)
{
    int idx = blockIdx.x * blockDim.x + threadIdx.x;
    if (idx >= NV * DD) return;
    int v = idx / DD, j = idx % DD;
    float cnt = fmaxf(g_cnt[v], 1.f);
    float acc = g_agg[idx] / cnt + bias[j];
    const float* xr = xin + (size_t)v * DD;
    #pragma unroll
    for (int i = 0; i < DD; i++) acc += xr[i] * root[i * DD + j];
    if (doRelu) acc = fmaxf(acc, 0.f);
    xout[idx] = acc;
}

// ---------------- Set2Set: one full step (LSTM + attention) ---------------
__device__ __forceinline__ float sigm(float v) { return 1.f / (1.f + expf(-v)); }

__global__ void __launch_bounds__(128) s2s_step_kernel(
    const float* __restrict__ x2,
    const float* __restrict__ wih, const float* __restrict__ whh,
    const float* __restrict__ bih, const float* __restrict__ bhh)
{
    __shared__ float sq[2 * DD], shh[DD], scc[DD], sg[4 * DD], hn[DD];
    __shared__ float red[128];
    __shared__ float wr[4][DD];
    __shared__ float ws[4];

    int b = blockIdx.x, t = threadIdx.x;
    if (t < 2 * DD) sq[t] = g_qstar[b * 2 * DD + t];
    if (t < DD) { shh[t] = g_h[b * DD + t]; scc[t] = g_c[b * DD + t]; }
    __syncthreads();

    if (t < 4 * DD) {
        float g = bih[t] + bhh[t];
        #pragma unroll 8
        for (int u = 0; u < 2 * DD; u++) g += sq[u] * wih[t * 2 * DD + u];
        #pragma unroll 8
        for (int u = 0; u < DD; u++) g += shh[u] * whh[t * DD + u];
        sg[t] = g;
    }
    __syncthreads();

    if (t < DD) {
        float ig = sigm(sg[t]);
        float fg = sigm(sg[DD + t]);
        float gg = tanhf(sg[2 * DD + t]);
        float og = sigm(sg[3 * DD + t]);
        float cn = fg * scc[t] + ig * gg;
        float hv = og * tanhf(cn);
        g_c[b * DD + t] = cn;
        g_h[b * DD + t] = hv;
        hn[t] = hv;
    }
    __syncthreads();

    int s0 = g_start[b], s1 = g_start[b + 1];

    float lmax = -3.4e38f;
    for (int n = s0 + t; n < s1; n += 128) {
        const float* xr = x2 + (size_t)n * DD;
        float e = 0.f;
        #pragma unroll
        for (int d = 0; d < DD; d++) e += xr[d] * hn[d];
        lmax = fmaxf(lmax, e);
    }
    red[t] = lmax;
    __syncthreads();
    for (int s = 64; s > 0; s >>= 1) {
        if (t < s) red[t] = fmaxf(red[t], red[t + s]);
        __syncthreads();
    }
    float emax = red[0];
    if (!(emax > -3.0e38f)) emax = 0.f;

    float lsum = 0.f;
    float lr[DD];
    #pragma unroll
    for (int d = 0; d < DD; d++) lr[d] = 0.f;
    for (int n = s0 + t; n < s1; n += 128) {
        const float* xr = x2 + (size_t)n * DD;
        float e = 0.f;
        #pragma unroll
        for (int d = 0; d < DD; d++) e += xr[d] * hn[d];
        float ex = expf(e - emax);
        lsum += ex;
        #pragma unroll
        for (int d = 0; d < DD; d++) lr[d] += ex * xr[d];
    }
    #pragma unroll
    for (int o = 16; o > 0; o >>= 1) {
        lsum += __shfl_xor_sync(0xffffffffu, lsum, o);
        #pragma unroll
        for (int d = 0; d < DD; d++) lr[d] += __shfl_xor_sync(0xffffffffu, lr[d], o);
    }
    int wid = t >> 5, lane = t & 31;
    if (lane == 0) ws[wid] = lsum;
    if (lane < DD) wr[wid][lane] = lr[lane];
    __syncthreads();

    if (t < DD) {
        float denom = ws[0] + ws[1] + ws[2] + ws[3];
        float rsum = wr[0][t] + wr[1][t] + wr[2][t] + wr[3][t];
        float r = rsum / fmaxf(denom, 1e-16f);
        g_qstar[b * 2 * DD + t] = hn[t];
        g_qstar[b * 2 * DD + DD + t] = r;
    }
}

// ---------------- heads ----------------
__global__ void heads_kernel(const float* __restrict__ wfc2, const float* __restrict__ bfc2,
                             const float* __restrict__ wfc3, const float* __restrict__ bfc3,
                             float* __restrict__ out)
{
    int b = blockIdx.x * blockDim.x + threadIdx.x;
    if (b >= NB) return;
    const float* q = g_qstar + b * 2 * DD;
    float hid[8];
    #pragma unroll
    for (int j = 0; j < 8; j++) {
        float h = bfc2[j];
        #pragma unroll 8
        for (int u = 0; u < 2 * DD; u++) h += q[u] * wfc2[u * 8 + j];
        hid[j] = fmaxf(h, 0.f);
    }
    #pragma unroll
    for (int k = 0; k < 2; k++) {
        float o = bfc3[k];
        #pragma unroll
        for (int j = 0; j < 8; j++) o += hid[j] * wfc3[j * 2 + k];
        out[b * 2 + k] = o;
    }
}

// ---------------- launch ----------------
extern "C" void kernel_launch(void* const* d_in, const int* in_sizes, int n_in,
                              void* d_out, int out_size)
{
    const float* x        = (const float*)d_in[0];
    const float* ea       = (const float*)d_in[1];
    const float* w_e1     = (const float*)d_in[2];
    const float* b_e1     = (const float*)d_in[3];
    const float* w_e2     = (const float*)d_in[4];
    const float* b_e2     = (const float*)d_in[5];
    const float* root     = (const float*)d_in[6];
    const float* bias_c   = (const float*)d_in[7];
    const float* w_ih     = (const float*)d_in[8];
    const float* w_hh     = (const float*)d_in[9];
    const float* b_ih     = (const float*)d_in[10];
    const float* b_hh     = (const float*)d_in[11];
    const float* w_fc2    = (const float*)d_in[12];
    const float* b_fc2    = (const float*)d_in[13];
    const float* w_fc3    = (const float*)d_in[14];
    const float* b_fc3    = (const float*)d_in[15];
    const int*   ei       = (const int*)d_in[16];
    const int*   bat      = (const int*)d_in[17];
    float* out            = (float*)d_out;

    float *px1 = nullptr, *px2 = nullptr;
    cudaGetSymbolAddress((void**)&px1, g_x1);
    cudaGetSymbolAddress((void**)&px2, g_x2);
    cudaFuncSetAttribute(gemm_we_kernel,
                         cudaFuncAttributeMaxDynamicSharedMemorySize, 4 * STG_SZ);

    zero_all_kernel<<<1024, 256>>>(w_e2);          // also converts W2 -> bf16 hi/lo
    edge_mlp1_kernel<<<NE / 8, 128>>>(ea, w_e1, b_e1);
    graph_bounds_kernel<<<(NV + 255) / 256, 256>>>(bat);
    {
        dim3 grid(NTC, MT);   // 3 x 1563
        gemm_we_kernel<<<grid, 256, 4 * STG_SZ>>>(b_e2);
    }

    // NNConv layer 1 (input x, relu -> g_x1)
    msg_pass_kernel<<<NE / 8, 256>>>(x, ei, 1);
    node_update_kernel<<<(NV * DD + 255) / 256, 256>>>(x, root, bias_c, px1, 1);

    // NNConv layer 2 (input g_x1 -> g_x2)
    zero_agg_kernel<<<512, 256>>>();
    msg_pass_kernel<<<NE / 8, 256>>>(px1, ei, 0);
    node_update_kernel<<<(NV * DD + 255) / 256, 256>>>(px1, root, bias_c, px2, 0);

    // Set2Set: 3 steps
    for (int s = 0; s < 3; s++)
        s2s_step_kernel<<<NB, 128>>>(px2, w_ih, w_hh, b_ih, b_hh);

    heads_kernel<<<(NB + 255) / 256, 256>>>(w_fc2, b_fc2, w_fc3, b_fc3, out);
}

// round 16
// speedup vs baseline: 1.6806x; 1.0334x over previous
#include <cuda_runtime.h>
#include <cuda_bf16.h>
#include <cstdint>

// ---------------- problem constants ----------------
#define NV      50000      // nodes
#define NE      200000     // edges
#define NB      1024       // graphs
#define DD      24         // node feature dim
#define EF      8          // edge feature dim
#define EH      128        // edge MLP hidden
#define DW      576        // D*D
#define MT      1563       // m-tiles of 128 edges
#define ME_PAD  (MT*128)   // 200064 padded edge rows
#define BN      96         // n per CTA
#define NTC     6          // n-tiles of 96 over DW=576

// ---------------- device scratch (zero-init at module load) ----------------
__device__ __align__(16) __nv_bfloat16 g_Hhi[(size_t)ME_PAD * EH];  // 51.2 MB
__device__ __align__(16) __nv_bfloat16 g_Hlo[(size_t)ME_PAD * EH];  // 51.2 MB
__device__ __align__(16) __nv_bfloat16 g_Bhi[EH * DW];              // 144 KB
__device__ __align__(16) __nv_bfloat16 g_Blo[EH * DW];              // 144 KB
__device__ float g_We[(size_t)ME_PAD * DW];    // 461 MB per-edge 24x24 weights
__device__ float g_agg[NV * DD];
__device__ float g_cnt[NV];
__device__ float g_x1[NV * DD];
__device__ float g_x2[NV * DD];
__device__ int   g_start[NB + 1];
__device__ float g_qstar[NB * 2 * DD];
__device__ float g_h[NB * DD];
__device__ float g_c[NB * DD];

// ---------------- zero + W2 bf16-split conversion (fused) ----------------
__global__ void zero_all_kernel(const float* __restrict__ w_e2) {
    int i = blockIdx.x * blockDim.x + threadIdx.x;
    int stride = gridDim.x * blockDim.x;
    for (int k = i; k < NV * DD; k += stride) g_agg[k] = 0.f;
    for (int k = i; k < NV; k += stride) g_cnt[k] = 0.f;
    for (int k = i; k < NB * 2 * DD; k += stride) g_qstar[k] = 0.f;
    for (int k = i; k < NB * DD; k += stride) { g_h[k] = 0.f; g_c[k] = 0.f; }
    for (int k = i; k < EH * DW; k += stride) {
        float v = w_e2[k];
        __nv_bfloat16 hi = __float2bfloat16(v);
        g_Bhi[k] = hi;
        g_Blo[k] = __float2bfloat16(v - __bfloat162float(hi));
    }
}
__global__ void zero_agg_kernel() {
    int i = blockIdx.x * blockDim.x + threadIdx.x;
    int stride = gridDim.x * blockDim.x;
    for (int k = i; k < NV * DD; k += stride) g_agg[k] = 0.f;
}

// ---------------- stage A1: H = relu(ea@W1+b1) -> bf16 hi/lo --------------
__global__ void __launch_bounds__(128) edge_mlp1_kernel(
    const float* __restrict__ ea, const float* __restrict__ w1,
    const float* __restrict__ b1)
{
    __shared__ float sw[EF * EH];
    __shared__ float sb[EH];
    __shared__ float sea[8 * EF];
    int t = threadIdx.x;
    for (int i = t; i < EF * EH; i += 128) sw[i] = w1[i];
    sb[t] = b1[t];
    int e0 = blockIdx.x * 8;
    for (int i = t; i < 8 * EF; i += 128) {
        int ee = e0 + i / EF;
        if (ee < NE) sea[i] = ea[(size_t)ee * EF + (i % EF)];
    }
    __syncthreads();
    #pragma unroll
    for (int q = 0; q < 8; q++) {
        int e = e0 + q;
        if (e >= NE) break;
        float acc = sb[t];
        #pragma unroll
        for (int i = 0; i < EF; i++) acc += sea[q * EF + i] * sw[i * EH + t];
        acc = fmaxf(acc, 0.f);
        __nv_bfloat16 hi = __float2bfloat16(acc);
        g_Hhi[(size_t)e * EH + t] = hi;
        g_Hlo[(size_t)e * EH + t] = __float2bfloat16(acc - __bfloat162float(hi));
    }
}

// ---------------- stage A2: We = H @ W2 + b2  (mma.sync bf16 split) -------
// CTA: 128(M) x 96(N) x K128, 256 threads, 8 warps (4m x 2n), warp 32x48.
// 2-stage cp.async ring (28KB/stage, 56KB total) -> 2 CTAs/SM for cross-CTA
// overlap. Grid x = bn (6 CTAs share one A m-tile via L2).
#define STG_SZ   28672
#define OFF_AHI  0
#define OFF_ALO  8192
#define OFF_BHI  16384
#define OFF_BLO  22528

__device__ __forceinline__ uint32_t smem_u32(const void* p) {
    uint32_t a;
    asm("{ .reg .u64 t; cvta.to.shared.u64 t, %1; cvt.u32.u64 %0, t; }" : "=r"(a) : "l"(p));
    return a;
}
#define CPA16(dst, src) \
    asm volatile("cp.async.cg.shared.global [%0], [%1], 16;" :: "r"(dst), "l"(src) : "memory")
#define CPA_COMMIT() asm volatile("cp.async.commit_group;" ::: "memory")
#define CPA_WAIT(n)  asm volatile("cp.async.wait_group %0;" :: "n"(n) : "memory")

#define LDSM4(r, addr) \
    asm volatile("ldmatrix.sync.aligned.m8n8.x4.shared.b16 {%0,%1,%2,%3}, [%4];" \
        : "=r"((r)[0]), "=r"((r)[1]), "=r"((r)[2]), "=r"((r)[3]) : "r"(addr))
#define LDSM4T(r, addr) \
    asm volatile("ldmatrix.sync.aligned.m8n8.x4.trans.shared.b16 {%0,%1,%2,%3}, [%4];" \
        : "=r"((r)[0]), "=r"((r)[1]), "=r"((r)[2]), "=r"((r)[3]) : "r"(addr))
#define MMA16816(d, a, b0, b1) \
    asm volatile("mma.sync.aligned.m16n8k16.row.col.f32.bf16.bf16.f32 " \
        "{%0,%1,%2,%3}, {%4,%5,%6,%7}, {%8,%9}, {%0,%1,%2,%3};" \
        : "+f"((d)[0]), "+f"((d)[1]), "+f"((d)[2]), "+f"((d)[3]) \
        : "r"((a)[0]), "r"((a)[1]), "r"((a)[2]), "r"((a)[3]), "r"(b0), "r"(b1))

__global__ void __launch_bounds__(256, 2) gemm_we_kernel(
    const float* __restrict__ be2)
{
    extern __shared__ __align__(16) char smem[];
    uint32_t sb = smem_u32(smem);

    int t = threadIdx.x;
    int lane = t & 31, wid = t >> 5;
    int warp_m = wid & 3, warp_n = wid >> 2;
    int bn = blockIdx.x, bm = blockIdx.y;

    float acc[2][6][4];
    #pragma unroll
    for (int f = 0; f < 2; f++)
        #pragma unroll
        for (int g = 0; g < 6; g++)
            #pragma unroll
            for (int i = 0; i < 4; i++) acc[f][g][i] = 0.f;

    // staging indices (stage-invariant)
    const int amb = t >> 5;              // + p*8
    const int akb = (t >> 3) & 3;
    const int am8 = t & 7;

    const char* HhiB = (const char*)g_Hhi;
    const char* HloB = (const char*)g_Hlo;
    const char* BhiB = (const char*)g_Bhi;
    const char* BloB = (const char*)g_Blo;

    // ---- stage loader ----
    #define STAGE_LOAD(s) do {                                                  \
        int _k0 = (s) * 32;                                                     \
        uint32_t _base = sb + ((s) & 1) * STG_SZ;                               \
        _Pragma("unroll")                                                       \
        for (int p = 0; p < 2; p++) {                                           \
            int c = t + p * 256;                                                \
            int mb = amb + p * 8;                                               \
            size_t e = (size_t)bm * 128 + mb * 8 + am8;                         \
            size_t so = (e * EH + _k0 + akb * 8) * 2;                           \
            CPA16(_base + OFF_AHI + c * 16, HhiB + so);                         \
            CPA16(_base + OFF_ALO + c * 16, HloB + so);                         \
        }                                                                       \
        _Pragma("unroll")                                                       \
        for (int p = 0; p < 2; p++) {                                           \
            int c = t + p * 256;                                                \
            if (c < 384) {                                                      \
                int kb = c / 96;                                                \
                int rem = c - kb * 96;                                          \
                int nb = rem >> 3, k8 = rem & 7;                                \
                size_t k = (size_t)_k0 + kb * 8 + k8;                           \
                size_t so = (k * DW + bn * BN + nb * 8) * 2;                    \
                uint32_t doff = (uint32_t)(((kb * 12 + nb) * 8 + k8) * 16);     \
                CPA16(_base + OFF_BHI + doff, BhiB + so);                       \
                CPA16(_base + OFF_BLO + doff, BloB + so);                       \
            }                                                                   \
        }                                                                       \
        CPA_COMMIT();                                                           \
    } while (0)

    STAGE_LOAD(0);
    STAGE_LOAD(1);

    #pragma unroll
    for (int s = 0; s < 4; s++) {
        if (s < 3) { CPA_WAIT(1); } else { CPA_WAIT(0); }
        __syncthreads();

        uint32_t base = sb + (s & 1) * STG_SZ;
        #pragma unroll
        for (int ks = 0; ks < 2; ks++) {
            uint32_t ahi[2][4], alo[2][4];
            #pragma unroll
            for (int f = 0; f < 2; f++) {
                int mb = warp_m * 4 + f * 2 + ((lane >> 3) & 1);
                int kb = ks * 2 + ((lane >> 4) & 1);
                uint32_t off = (uint32_t)(((mb * 4 + kb) * 8 + (lane & 7)) * 16);
                LDSM4(ahi[f], base + OFF_AHI + off);
                LDSM4(alo[f], base + OFF_ALO + off);
            }
            #pragma unroll
            for (int g2 = 0; g2 < 3; g2++) {
                uint32_t bhi[4], blo[4];
                int kb = ks * 2 + ((lane >> 3) & 1);
                int nb = warp_n * 6 + g2 * 2 + ((lane >> 4) & 1);
                uint32_t off = (uint32_t)(((kb * 12 + nb) * 8 + (lane & 7)) * 16);
                LDSM4T(bhi, base + OFF_BHI + off);
                LDSM4T(blo, base + OFF_BLO + off);
                #pragma unroll
                for (int f = 0; f < 2; f++)
                    #pragma unroll
                    for (int gg = 0; gg < 2; gg++) {
                        float* a4 = acc[f][g2 * 2 + gg];
                        MMA16816(a4, ahi[f], bhi[gg * 2], bhi[gg * 2 + 1]);  // hi*hi
                        MMA16816(a4, alo[f], bhi[gg * 2], bhi[gg * 2 + 1]);  // lo*hi
                        MMA16816(a4, ahi[f], blo[gg * 2], blo[gg * 2 + 1]);  // hi*lo
                    }
            }
        }
        if (s < 2) {
            __syncthreads();      // all warps done reading buffer (s&1)
            STAGE_LOAD(s + 2);
        }
    }

    // ---- epilogue: add bias, store fp32 ----
    int r0 = lane >> 2, c0 = (lane & 3) * 2;
    #pragma unroll
    for (int g = 0; g < 6; g++) {
        int col = bn * BN + warp_n * 48 + g * 8 + c0;
        float bx = be2[col], by = be2[col + 1];
        #pragma unroll
        for (int f = 0; f < 2; f++) {
            size_t row = (size_t)bm * 128 + warp_m * 32 + f * 16 + r0;
            float2 v0 = make_float2(acc[f][g][0] + bx, acc[f][g][1] + by);
            float2 v1 = make_float2(acc[f][g][2] + bx, acc[f][g][3] + by);
            *reinterpret_cast<float2*>(&g_We[row * DW + col]) = v0;
            *reinterpret_cast<float2*>(&g_We[(row + 8) * DW + col]) = v1;
        }
    }
}

// ---------------- graph boundaries from sorted batch (int32) -------------
__global__ void graph_bounds_kernel(const int* __restrict__ batch) {
    int i = blockIdx.x * blockDim.x + threadIdx.x;
    if (i >= NV) return;
    int bi = batch[i];
    if (i == 0) {
        for (int g = 0; g <= bi; g++) g_start[g] = 0;
    } else {
        int bp = batch[i - 1];
        for (int g = bp + 1; g <= bi; g++) g_start[g] = i;
    }
    if (i == NV - 1) {
        for (int g = bi + 1; g <= NB; g++) g_start[g] = NV;
    }
}

// ---------------- message pass: agg[dst] += x[src] @ We[e] ----------------
__global__ void msg_pass_kernel(const float* __restrict__ x,
                                const int* __restrict__ ei, int addCnt)
{
    int w = (blockIdx.x * blockDim.x + threadIdx.x) >> 5;
    int lane = threadIdx.x & 31;
    if (w >= NE) return;
    int src = ei[w];
    int dst = ei[NE + w];
    float xv = (lane < DD) ? x[(size_t)src * DD + lane] : 0.f;
    float acc = 0.f;
    const float* We = g_We + (size_t)w * DW;
    #pragma unroll
    for (int i = 0; i < DD; i++) {
        float xi = __shfl_sync(0xffffffffu, xv, i);
        float wv = (lane < DD) ? We[i * DD + lane] : 0.f;
        acc += xi * wv;
    }
    if (lane < DD) atomicAdd(&g_agg[dst * DD + lane], acc);
    if (addCnt && lane == 0) atomicAdd(&g_cnt[dst], 1.f);
}

// ---------------- node update: agg/cnt + x@root + bias (opt relu) ---------
__global__ void node_update_kernel(const float* __restrict__ xin,
                                   const float* __restrict__ root,
                                   const float* __restrict__ bias,
                                   float* __restrict__ xout, int doRelu)
{
    int idx = blockIdx.x * blockDim.x + threadIdx.x;
    if (idx >= NV * DD) return;
    int v = idx / DD, j = idx % DD;
    float cnt = fmaxf(g_cnt[v], 1.f);
    float acc = g_agg[idx] / cnt + bias[j];
    const float* xr = xin + (size_t)v * DD;
    #pragma unroll
    for (int i = 0; i < DD; i++) acc += xr[i] * root[i * DD + j];
    if (doRelu) acc = fmaxf(acc, 0.f);
    xout[idx] = acc;
}

// ---------------- Set2Set: one full step (LSTM + attention) ---------------
__device__ __forceinline__ float sigm(float v) { return 1.f / (1.f + expf(-v)); }

__global__ void __launch_bounds__(128) s2s_step_kernel(
    const float* __restrict__ x2,
    const float* __restrict__ wih, const float* __restrict__ whh,
    const float* __restrict__ bih, const float* __restrict__ bhh)
{
    __shared__ float sq[2 * DD], shh[DD], scc[DD], sg[4 * DD], hn[DD];
    __shared__ float red[128];
    __shared__ float wr[4][DD];
    __shared__ float ws[4];

    int b = blockIdx.x, t = threadIdx.x;
    if (t < 2 * DD) sq[t] = g_qstar[b * 2 * DD + t];
    if (t < DD) { shh[t] = g_h[b * DD + t]; scc[t] = g_c[b * DD + t]; }
    __syncthreads();

    if (t < 4 * DD) {
        float g = bih[t] + bhh[t];
        #pragma unroll 8
        for (int u = 0; u < 2 * DD; u++) g += sq[u] * wih[t * 2 * DD + u];
        #pragma unroll 8
        for (int u = 0; u < DD; u++) g += shh[u] * whh[t * DD + u];
        sg[t] = g;
    }
    __syncthreads();

    if (t < DD) {
        float ig = sigm(sg[t]);
        float fg = sigm(sg[DD + t]);
        float gg = tanhf(sg[2 * DD + t]);
        float og = sigm(sg[3 * DD + t]);
        float cn = fg * scc[t] + ig * gg;
        float hv = og * tanhf(cn);
        g_c[b * DD + t] = cn;
        g_h[b * DD + t] = hv;
        hn[t] = hv;
    }
    __syncthreads();

    int s0 = g_start[b], s1 = g_start[b + 1];

    float lmax = -3.4e38f;
    for (int n = s0 + t; n < s1; n += 128) {
        const float* xr = x2 + (size_t)n * DD;
        float e = 0.f;
        #pragma unroll
        for (int d = 0; d < DD; d++) e += xr[d] * hn[d];
        lmax = fmaxf(lmax, e);
    }
    red[t] = lmax;
    __syncthreads();
    for (int s = 64; s > 0; s >>= 1) {
        if (t < s) red[t] = fmaxf(red[t], red[t + s]);
        __syncthreads();
    }
    float emax = red[0];
    if (!(emax > -3.0e38f)) emax = 0.f;

    float lsum = 0.f;
    float lr[DD];
    #pragma unroll
    for (int d = 0; d < DD; d++) lr[d] = 0.f;
    for (int n = s0 + t; n < s1; n += 128) {
        const float* xr = x2 + (size_t)n * DD;
        float e = 0.f;
        #pragma unroll
        for (int d = 0; d < DD; d++) e += xr[d] * hn[d];
        float ex = expf(e - emax);
        lsum += ex;
        #pragma unroll
        for (int d = 0; d < DD; d++) lr[d] += ex * xr[d];
    }
    #pragma unroll
    for (int o = 16; o > 0; o >>= 1) {
        lsum += __shfl_xor_sync(0xffffffffu, lsum, o);
        #pragma unroll
        for (int d = 0; d < DD; d++) lr[d] += __shfl_xor_sync(0xffffffffu, lr[d], o);
    }
    int wid = t >> 5, lane = t & 31;
    if (lane == 0) ws[wid] = lsum;
    if (lane < DD) wr[wid][lane] = lr[lane];
    __syncthreads();

    if (t < DD) {
        float denom = ws[0] + ws[1] + ws[2] + ws[3];
        float rsum = wr[0][t] + wr[1][t] + wr[2][t] + wr[3][t];
        float r = rsum / fmaxf(denom, 1e-16f);
        g_qstar[b * 2 * DD + t] = hn[t];
        g_qstar[b * 2 * DD + DD + t] = r;
    }
}

// ---------------- heads ----------------
__global__ void heads_kernel(const float* __restrict__ wfc2, const float* __restrict__ bfc2,
                             const float* __restrict__ wfc3, const float* __restrict__ bfc3,
                             float* __restrict__ out)
{
    int b = blockIdx.x * blockDim.x + threadIdx.x;
    if (b >= NB) return;
    const float* q = g_qstar + b * 2 * DD;
    float hid[8];
    #pragma unroll
    for (int j = 0; j < 8; j++) {
        float h = bfc2[j];
        #pragma unroll 8
        for (int u = 0; u < 2 * DD; u++) h += q[u] * wfc2[u * 8 + j];
        hid[j] = fmaxf(h, 0.f);
    }
    #pragma unroll
    for (int k = 0; k < 2; k++) {
        float o = bfc3[k];
        #pragma unroll
        for (int j = 0; j < 8; j++) o += hid[j] * wfc3[j * 2 + k];
        out[b * 2 + k] = o;
    }
}

// ---------------- launch ----------------
extern "C" void kernel_launch(void* const* d_in, const int* in_sizes, int n_in,
                              void* d_out, int out_size)
{
    const float* x        = (const float*)d_in[0];
    const float* ea       = (const float*)d_in[1];
    const float* w_e1     = (const float*)d_in[2];
    const float* b_e1     = (const float*)d_in[3];
    const float* w_e2     = (const float*)d_in[4];
    const float* b_e2     = (const float*)d_in[5];
    const float* root     = (const float*)d_in[6];
    const float* bias_c   = (const float*)d_in[7];
    const float* w_ih     = (const float*)d_in[8];
    const float* w_hh     = (const float*)d_in[9];
    const float* b_ih     = (const float*)d_in[10];
    const float* b_hh     = (const float*)d_in[11];
    const float* w_fc2    = (const float*)d_in[12];
    const float* b_fc2    = (const float*)d_in[13];
    const float* w_fc3    = (const float*)d_in[14];
    const float* b_fc3    = (const float*)d_in[15];
    const int*   ei       = (const int*)d_in[16];
    const int*   bat      = (const int*)d_in[17];
    float* out            = (float*)d_out;

    float *px1 = nullptr, *px2 = nullptr;
    cudaGetSymbolAddress((void**)&px1, g_x1);
    cudaGetSymbolAddress((void**)&px2, g_x2);
    cudaFuncSetAttribute(gemm_we_kernel,
                         cudaFuncAttributeMaxDynamicSharedMemorySize, 2 * STG_SZ);

    zero_all_kernel<<<1024, 256>>>(w_e2);          // also converts W2 -> bf16 hi/lo
    edge_mlp1_kernel<<<NE / 8, 128>>>(ea, w_e1, b_e1);
    graph_bounds_kernel<<<(NV + 255) / 256, 256>>>(bat);
    {
        dim3 grid(NTC, MT);   // 6 x 1563, bn fastest (A tile shared via L2)
        gemm_we_kernel<<<grid, 256, 2 * STG_SZ>>>(b_e2);
    }

    // NNConv layer 1 (input x, relu -> g_x1)
    msg_pass_kernel<<<NE / 8, 256>>>(x, ei, 1);
    node_update_kernel<<<(NV * DD + 255) / 256, 256>>>(x, root, bias_c, px1, 1);

    // NNConv layer 2 (input g_x1 -> g_x2)
    zero_agg_kernel<<<512, 256>>>();
    msg_pass_kernel<<<NE / 8, 256>>>(px1, ei, 0);
    node_update_kernel<<<(NV * DD + 255) / 256, 256>>>(px1, root, bias_c, px2, 0);

    // Set2Set: 3 steps
    for (int s = 0; s < 3; s++)
        s2s_step_kernel<<<NB, 128>>>(px2, w_ih, w_hh, b_ih, b_hh);

    heads_kernel<<<(NB + 255) / 256, 256>>>(w_fc2, b_fc2, w_fc3, b_fc3, out);
}